// round 14
// baseline (speedup 1.0000x reference)
#include <cuda_runtime.h>
#include <cuda_fp16.h>
#include <cuda_bf16.h>
#include <math.h>
#include <stdint.h>

#define N_NODES 16384
#define N_EDGES 32768
#define NG 256
#define TPG 12
#define NT (NG*TPG)
#define D 64
#define BK 192          // split-bf16 K extent (3 x 64)

__device__ float  g_out[N_NODES*D];
__device__ __nv_bfloat16 g_outb[(size_t)N_NODES*BK];   // split-bf16 of out/h  [hi|lo|hi]
__device__ __nv_bfloat16 g_mb  [(size_t)N_NODES*BK];   // split-bf16 of m      [hi|lo|hi]
__device__ __nv_bfloat16 g_heb[(size_t)N_EDGES*BK];
__device__ __nv_bfloat16 g_w2b[4096*BK];
__device__ __nv_bfloat16 g_wihb[192*BK];               // split-B [hi|hi|lo]
__device__ __nv_bfloat16 g_whhb[192*BK];
__device__ __half g_ew [(size_t)N_EDGES*D*D];
__device__ float  g_msg[(size_t)N_EDGES*D];            // stored in CSR position order
__device__ float  g_gi [N_NODES*3*D];
__device__ float  g_gh [N_NODES*3*D];
__device__ int    g_cnt[N_NODES];
__device__ int    g_eoff[N_NODES+1];
__device__ int    g_eid[N_EDGES];
__device__ float  g_s2s_wih_t[2*D*4*D];
__device__ float  g_s2s_whh_t[D*4*D];
__device__ float  g_mem_wih_t[2*D*4*D];
__device__ float  g_lin1_t[5*D*D];
__device__ float  g_hx[NG*D];

__device__ __forceinline__ float sigf(float x) { return 1.0f/(1.0f+expf(-x)); }

__device__ __forceinline__ uint32_t smem_to_u32(const void* p) {
    uint32_t a;
    asm("{ .reg .u64 t; cvta.to.shared.u64 t, %1; cvt.u32.u64 %0, t; }" : "=r"(a) : "l"(p));
    return a;
}

// ---------------- merged prologue ----------------
__global__ void k_prep_all(const float* __restrict__ gru_wih, const float* __restrict__ gru_whh,
                           const float* __restrict__ s2s_wih, const float* __restrict__ s2s_whh,
                           const float* __restrict__ mem_wih, const float* __restrict__ lin1_w,
                           const float* __restrict__ e2_w,
                           const float* __restrict__ x, const float* __restrict__ lin0_w,
                           const float* __restrict__ lin0_b,
                           const float* __restrict__ ea, const float* __restrict__ e1_w,
                           const float* __restrict__ e1_b)
{
    int i = blockIdx.x*blockDim.x + threadIdx.x;
    if (i < 4096*64) {
        int n = i >> 6, k = i & 63;
        float v = e2_w[i];
        __nv_bfloat16 hi = __float2bfloat16(v);
        __nv_bfloat16 lo = __float2bfloat16(v - __bfloat162float(hi));
        g_w2b[n*BK + k]       = hi;
        g_w2b[n*BK + 64 + k]  = hi;
        g_w2b[n*BK + 128 + k] = lo;
    }
    if (i < 192*64) {
        int j = i >> 6, k = i & 63;
        float wv = gru_wih[i];
        __nv_bfloat16 hi = __float2bfloat16(wv);
        __nv_bfloat16 lo = __float2bfloat16(wv - __bfloat162float(hi));
        g_wihb[j*BK + k]       = hi;
        g_wihb[j*BK + 64 + k]  = hi;
        g_wihb[j*BK + 128 + k] = lo;
        float wh = gru_whh[i];
        __nv_bfloat16 hh = __float2bfloat16(wh);
        __nv_bfloat16 hl = __float2bfloat16(wh - __bfloat162float(hh));
        g_whhb[j*BK + k]       = hh;
        g_whhb[j*BK + 64 + k]  = hh;
        g_whhb[j*BK + 128 + k] = hl;
    }
    if (i < 128*256) { int k = i/256,  j = i%256;  g_s2s_wih_t[i] = s2s_wih[j*128+k];
                                                   g_mem_wih_t[i] = mem_wih[j*128+k]; }
    if (i < 64*256)  { int k = i/256,  j = i%256;  g_s2s_whh_t[i] = s2s_whh[j*64+k]; }
    if (i < 320*64)  { int q = i/64,   j = i%64;   g_lin1_t[i] = lin1_w[j*320+q]; }
    if (i < N_NODES) g_cnt[i] = 0;
    if (i < N_NODES*D) {
        int n = i >> 6, j = i & 63;
        float acc = lin0_b[j];
        #pragma unroll
        for (int k = 0; k < 3; k++) acc += x[n*3+k]*lin0_w[j*3+k];
        float v = fmaxf(acc, 0.f);
        g_out[i] = v;
        __nv_bfloat16 hi = __float2bfloat16(v);
        __nv_bfloat16 lo = __float2bfloat16(v - __bfloat162float(hi));
        size_t base = (size_t)n*BK;
        g_outb[base + j]       = hi;
        g_outb[base + 64 + j]  = lo;
        g_outb[base + 128 + j] = hi;
    }
    if (i < N_EDGES*D) {
        int e = i >> 6, j = i & 63;
        float acc = e1_b[j];
        #pragma unroll
        for (int k = 0; k < 6; k++) acc += ea[e*6+k]*e1_w[j*6+k];
        float v = fmaxf(acc, 0.f);
        __nv_bfloat16 hi = __float2bfloat16(v);
        __nv_bfloat16 lo = __float2bfloat16(v - __bfloat162float(hi));
        size_t base = (size_t)e*BK;
        g_heb[base + j]       = hi;
        g_heb[base + 64 + j]  = lo;
        g_heb[base + 128 + j] = hi;
    }
}

// ---------------- HMMA primitives ----------------
__device__ __forceinline__ void mma16816(float c[4], uint32_t a0, uint32_t a1, uint32_t a2, uint32_t a3,
                                         uint32_t b0, uint32_t b1)
{
    asm volatile(
        "mma.sync.aligned.m16n8k16.row.col.f32.bf16.bf16.f32 "
        "{%0,%1,%2,%3}, {%4,%5,%6,%7}, {%8,%9}, {%0,%1,%2,%3};"
        : "+f"(c[0]), "+f"(c[1]), "+f"(c[2]), "+f"(c[3])
        : "r"(a0), "r"(a1), "r"(a2), "r"(a3), "r"(b0), "r"(b1));
}

#define ROWB 400   // bytes per smem row: 4-bank shift/row -> LDSM conflict-free
#define CPITCH 136 // C-stage pitch in halfs

// ---------------- build of g_ew (HMMA plateau ~121 T-MAC/s) ----------------
__global__ void __launch_bounds__(128)
k_build_ew(const float* __restrict__ e2_b)
{
    extern __shared__ char smem[];
    char* sA = smem;
    char* sB = smem + 128*ROWB;
    uint32_t sab = smem_to_u32(smem);
    int tid = threadIdx.x;
    int wid = tid >> 5, lane = tid & 31;
    int e0 = blockIdx.x * 128;
    int n0 = blockIdx.y * 128;

    for (int idx = tid; idx < 128*24; idx += 128) {
        int row = idx / 24, c = idx % 24;
        *(uint4*)(sA + row*ROWB + c*16) = ((const uint4*)(g_heb + (size_t)(e0+row)*BK))[c];
        *(uint4*)(sB + row*ROWB + c*16) = ((const uint4*)(g_w2b + (size_t)(n0+row)*BK))[c];
    }
    __syncthreads();

    int wm = (wid & 1) * 64;
    int wn = (wid >> 1) * 64;
    int grp = lane >> 3;
    int l7  = lane & 7;
    uint32_t aoff = sab + (uint32_t)((wm + (grp & 1)*8 + l7)*ROWB + ((grp >> 1)*8)*2);
    uint32_t boff = sab + (uint32_t)(128*ROWB + (wn + (grp >> 1)*8 + l7)*ROWB + ((grp & 1)*8)*2);

    float acc[4][8][4] = {};
    #pragma unroll
    for (int ks = 0; ks < 12; ks++) {
        uint32_t kb2 = ks * 32;
        uint32_t af[4][4];
        #pragma unroll
        for (int mt = 0; mt < 4; mt++) {
            asm volatile("ldmatrix.sync.aligned.m8n8.x4.shared.b16 {%0,%1,%2,%3}, [%4];"
                : "=r"(af[mt][0]), "=r"(af[mt][1]), "=r"(af[mt][2]), "=r"(af[mt][3])
                : "r"(aoff + mt*16*ROWB + kb2));
        }
        uint32_t bf[8][2];
        #pragma unroll
        for (int np = 0; np < 4; np++) {
            uint32_t r0, r1, r2, r3;
            asm volatile("ldmatrix.sync.aligned.m8n8.x4.shared.b16 {%0,%1,%2,%3}, [%4];"
                : "=r"(r0), "=r"(r1), "=r"(r2), "=r"(r3)
                : "r"(boff + np*16*ROWB + kb2));
            bf[np*2][0] = r0; bf[np*2][1] = r1;
            bf[np*2+1][0] = r2; bf[np*2+1][1] = r3;
        }
        #pragma unroll
        for (int mt = 0; mt < 4; mt++)
            #pragma unroll
            for (int nt = 0; nt < 8; nt++)
                mma16816(acc[mt][nt], af[mt][0], af[mt][1], af[mt][2], af[mt][3],
                         bf[nt][0], bf[nt][1]);
    }

    __syncthreads();
    __half* sC = (__half*)smem;
    int gr = lane >> 2;
    int cc = (lane & 3) * 2;
    #pragma unroll
    for (int nt = 0; nt < 8; nt++) {
        int col = wn + nt*8 + cc;
        float b0v = e2_b[n0 + col], b1v = e2_b[n0 + col + 1];
        #pragma unroll
        for (int mt = 0; mt < 4; mt++) {
            int r0 = wm + mt*16 + gr;
            *(__half2*)(sC + r0*CPITCH + col) =
                __floats2half2_rn(acc[mt][nt][0] + b0v, acc[mt][nt][1] + b1v);
            *(__half2*)(sC + (r0+8)*CPITCH + col) =
                __floats2half2_rn(acc[mt][nt][2] + b0v, acc[mt][nt][3] + b1v);
        }
    }
    __syncthreads();
    for (int idx = tid; idx < 128*16; idx += 128) {
        int row = idx >> 4, ch = idx & 15;
        uint4 v = *(const uint4*)(sC + row*CPITCH + ch*8);
        *(uint4*)(g_ew + (size_t)(e0+row)*4096 + n0 + ch*8) = v;
    }
}

// ---------------- HMMA gi/gh: grid (128, 3, 2) ----------
__global__ void __launch_bounds__(128)
k_gih_h(const float* __restrict__ bih, const float* __restrict__ bhh)
{
    extern __shared__ char smem[];
    char* sA = smem;
    char* sB = smem + 128*ROWB;
    uint32_t sab = smem_to_u32(smem);
    int tid = threadIdx.x;
    int wid = tid >> 5, lane = tid & 31;
    int e0 = blockIdx.x * 128;
    int j0 = blockIdx.y * 64;
    int half = blockIdx.z;
    const __nv_bfloat16* A = half ? g_outb : g_mb;
    const __nv_bfloat16* B = half ? g_whhb : g_wihb;
    const float* bias = half ? bhh : bih;
    float* C = half ? g_gh : g_gi;

    for (int idx = tid; idx < 128*24; idx += 128) {
        int row = idx / 24, c = idx % 24;
        *(uint4*)(sA + row*ROWB + c*16) = ((const uint4*)(A + (size_t)(e0+row)*BK))[c];
    }
    for (int idx = tid; idx < 64*24; idx += 128) {
        int row = idx / 24, c = idx % 24;
        *(uint4*)(sB + row*ROWB + c*16) = ((const uint4*)(B + (size_t)(j0+row)*BK))[c];
    }
    __syncthreads();

    int wm = (wid & 1) * 64;
    int wn = (wid >> 1) * 32;
    int grp = lane >> 3;
    int l7  = lane & 7;
    uint32_t aoff = sab + (uint32_t)((wm + (grp & 1)*8 + l7)*ROWB + ((grp >> 1)*8)*2);
    uint32_t boff = sab + (uint32_t)(128*ROWB + (wn + (grp >> 1)*8 + l7)*ROWB + ((grp & 1)*8)*2);

    float acc[4][4][4] = {};
    #pragma unroll
    for (int ks = 0; ks < 12; ks++) {
        uint32_t kb2 = ks * 32;
        uint32_t af[4][4];
        #pragma unroll
        for (int mt = 0; mt < 4; mt++) {
            asm volatile("ldmatrix.sync.aligned.m8n8.x4.shared.b16 {%0,%1,%2,%3}, [%4];"
                : "=r"(af[mt][0]), "=r"(af[mt][1]), "=r"(af[mt][2]), "=r"(af[mt][3])
                : "r"(aoff + mt*16*ROWB + kb2));
        }
        uint32_t bf[4][2];
        #pragma unroll
        for (int np = 0; np < 2; np++) {
            uint32_t r0, r1, r2, r3;
            asm volatile("ldmatrix.sync.aligned.m8n8.x4.shared.b16 {%0,%1,%2,%3}, [%4];"
                : "=r"(r0), "=r"(r1), "=r"(r2), "=r"(r3)
                : "r"(boff + np*16*ROWB + kb2));
            bf[np*2][0] = r0; bf[np*2][1] = r1;
            bf[np*2+1][0] = r2; bf[np*2+1][1] = r3;
        }
        #pragma unroll
        for (int mt = 0; mt < 4; mt++)
            #pragma unroll
            for (int nt = 0; nt < 4; nt++)
                mma16816(acc[mt][nt], af[mt][0], af[mt][1], af[mt][2], af[mt][3],
                         bf[nt][0], bf[nt][1]);
    }

    int gr = lane >> 2;
    int cc = (lane & 3) * 2;
    #pragma unroll
    for (int nt = 0; nt < 4; nt++) {
        int col = j0 + wn + nt*8 + cc;
        float b0v = bias[col], b1v = bias[col+1];
        #pragma unroll
        for (int mt = 0; mt < 4; mt++) {
            int r0 = e0 + wm + mt*16 + gr;
            *(float2*)(C + (size_t)r0*192 + col) =
                make_float2(acc[mt][nt][0] + b0v, acc[mt][nt][1] + b1v);
            *(float2*)(C + (size_t)(r0+8)*192 + col) =
                make_float2(acc[mt][nt][2] + b0v, acc[mt][nt][3] + b1v);
        }
    }
}

// ---------------- CSR build ----------------
__global__ void k_count(const int* __restrict__ dst)
{
    int e = blockIdx.x*blockDim.x + threadIdx.x;
    if (e < N_EDGES) atomicAdd(&g_cnt[dst[e]], 1);
}

// merged scan + fill (one block; smem offsets + counters)
__global__ void __launch_bounds__(1024) k_scanfill(const int* __restrict__ dst)
{
    extern __shared__ int sm[];               // [0:16384) eoff base, [16384:32768) cur
    int* seoff = sm;
    int* scur  = sm + N_NODES;
    __shared__ int part[1024];
    int tid = threadIdx.x;
    int base = tid*16;
    int loc[16]; int tsum = 0;
    #pragma unroll
    for (int t = 0; t < 16; t++) { loc[t] = g_cnt[base+t]; tsum += loc[t]; }
    part[tid] = tsum;
    __syncthreads();
    for (int d = 1; d < 1024; d <<= 1) {
        int v = 0;
        if (tid >= d) v = part[tid-d];
        __syncthreads();
        if (tid >= d) part[tid] += v;
        __syncthreads();
    }
    int run = part[tid] - tsum;
    #pragma unroll
    for (int t = 0; t < 16; t++) {
        seoff[base+t] = run;
        g_eoff[base+t] = run;
        scur[base+t] = 0;
        run += loc[t];
    }
    if (tid == 1023) g_eoff[N_NODES] = part[1023];
    __syncthreads();
    for (int e = tid; e < N_EDGES; e += 1024) {
        int d = dst[e];
        int p = atomicAdd(&scur[d], 1);
        g_eid[seoff[d] + p] = e;
    }
}

// ---------------- msg: CSR position order -> coalesced consumer reads ----------------
__global__ void __launch_bounds__(256)
k_msg_w(const int* __restrict__ src)
{
    __shared__ float s_o[8][64];
    int w = threadIdx.x >> 5;
    int lane = threadIdx.x & 31;
    int p = blockIdx.x*8 + w;
    int e = g_eid[p];
    int s = src[e];
    s_o[w][lane]      = g_out[s*64 + lane];
    s_o[w][lane + 32] = g_out[s*64 + 32 + lane];
    __syncwarp();
    int rgrp = lane >> 3;
    float acc[8] = {};
    const uint4* ew4 = (const uint4*)(g_ew + (size_t)e*4096);
    #pragma unroll
    for (int i = 0; i < 16; i++) {
        int row = i*4 + rgrp;
        uint4 v = ew4[i*32 + lane];
        float a = s_o[w][row];
        const __half2* hp = (const __half2*)&v;
        #pragma unroll
        for (int q = 0; q < 4; q++) {
            float2 f = __half22float2(hp[q]);
            acc[2*q]   += a*f.x;
            acc[2*q+1] += a*f.y;
        }
    }
    #pragma unroll
    for (int q = 0; q < 8; q++) {
        acc[q] += __shfl_xor_sync(0xffffffffu, acc[q], 8);
        acc[q] += __shfl_xor_sync(0xffffffffu, acc[q], 16);
    }
    if (lane < 8) {
        float4* op = (float4*)(g_msg + (size_t)p*64 + lane*8);
        op[0] = make_float4(acc[0], acc[1], acc[2], acc[3]);
        op[1] = make_float4(acc[4], acc[5], acc[6], acc[7]);
    }
}

// ---------------- node GEMM + contiguous CSR-mean; writes split-bf16 g_mb ----------------
__global__ void __launch_bounds__(256)
k_gemm1(const float* __restrict__ Bext, const float* __restrict__ bias)
{
    __shared__ __align__(16) float sAt[64][68];
    __shared__ __align__(16) float sB[64][64];
    int tid = threadIdx.x;
    int e0 = blockIdx.x * 64;
    for (int l = tid; l < 64*64; l += 256) {
        int r = l >> 6, c = l & 63;
        sAt[c][r] = g_out[(e0 + r)*64 + c];
        sB[r][c]  = Bext[r*64 + c];
    }
    __syncthreads();
    int te = (tid >> 4) << 2;
    int tj = (tid & 15) << 2;
    float acc[4][4] = {};
    #pragma unroll
    for (int k = 0; k < 64; k++) {
        float4 a = *(const float4*)&sAt[k][te];
        float4 b = *(const float4*)&sB[k][tj];
        acc[0][0] += a.x*b.x; acc[0][1] += a.x*b.y; acc[0][2] += a.x*b.z; acc[0][3] += a.x*b.w;
        acc[1][0] += a.y*b.x; acc[1][1] += a.y*b.y; acc[1][2] += a.y*b.z; acc[1][3] += a.y*b.w;
        acc[2][0] += a.z*b.x; acc[2][1] += a.z*b.y; acc[2][2] += a.z*b.z; acc[2][3] += a.z*b.w;
        acc[3][0] += a.w*b.x; acc[3][1] += a.w*b.y; acc[3][2] += a.w*b.z; acc[3][3] += a.w*b.w;
    }
    #pragma unroll
    for (int ii = 0; ii < 4; ii++) {
        int row = e0 + te + ii;
        int b0 = g_eoff[row], b1 = g_eoff[row+1];
        float s0 = 0.f, s1 = 0.f, s2 = 0.f, s3 = 0.f;
        for (int p = b0; p < b1; p++) {                      // contiguous rows of g_msg
            float4 v = *(const float4*)(g_msg + (size_t)p*64 + tj);
            s0 += v.x; s1 += v.y; s2 += v.z; s3 += v.w;
        }
        float inv = 1.0f/fmaxf((float)(b1 - b0), 1.f);
        float vals[4] = { fmaxf(acc[ii][0] + s0*inv + bias[tj+0], 0.f),
                          fmaxf(acc[ii][1] + s1*inv + bias[tj+1], 0.f),
                          fmaxf(acc[ii][2] + s2*inv + bias[tj+2], 0.f),
                          fmaxf(acc[ii][3] + s3*inv + bias[tj+3], 0.f) };
        size_t base = (size_t)row*BK;
        #pragma unroll
        for (int jj = 0; jj < 4; jj++) {
            float v = vals[jj];
            __nv_bfloat16 hi = __float2bfloat16(v);
            __nv_bfloat16 lo = __float2bfloat16(v - __bfloat162float(hi));
            g_mb[base + tj + jj]        = hi;
            g_mb[base + 64 + tj + jj]   = lo;
            g_mb[base + 128 + tj + jj]  = hi;
        }
    }
}

__global__ void k_gru()
{
    int i = blockIdx.x*blockDim.x + threadIdx.x;
    int n = i >> 6, j = i & 63;
    const float* gi = g_gi + n*192;
    const float* gh = g_gh + n*192;
    float r  = sigf(gi[j]      + gh[j]);
    float z  = sigf(gi[64+j]   + gh[64+j]);
    float nn = tanhf(gi[128+j] + r*gh[128+j]);
    float h  = g_out[i];
    float hn = (1.f - z)*nn + z*h;
    g_out[i] = hn;
    __nv_bfloat16 hi = __float2bfloat16(hn);
    __nv_bfloat16 lo = __float2bfloat16(hn - __bfloat162float(hi));
    size_t base = (size_t)n*BK;
    g_outb[base + j]       = hi;
    g_outb[base + 64 + j]  = lo;
    g_outb[base + 128 + j] = hi;
}

// Set2Set (6 steps) + memory LSTM; one block per graph
__global__ void __launch_bounds__(256)
k_s2s(const float* __restrict__ s2s_bih, const float* __restrict__ s2s_bhh,
      const float* __restrict__ mem_bih, const float* __restrict__ mem_bhh,
      float* __restrict__ d_out, int out_size)
{
    __shared__ float so[64*65];
    __shared__ float sq[128];
    __shared__ float shs[64], scs[64], sg[256], se[64];
    __shared__ float sred[2];
    int g = blockIdx.x, tid = threadIdx.x;
    for (int l = tid; l < 64*64; l += 256) {
        int n = l >> 6, c = l & 63;
        so[n*65+c] = g_out[(g*64+n)*64 + c];
    }
    if (tid < 128) sq[tid] = 0.f;
    if (tid < 64) { shs[tid] = 0.f; scs[tid] = 0.f; }
    __syncthreads();
    for (int step = 0; step < 6; step++) {
        float acc = s2s_bih[tid] + s2s_bhh[tid];
        #pragma unroll 4
        for (int k = 0; k < 128; k++) acc += sq[k]*g_s2s_wih_t[k*256+tid];
        #pragma unroll 4
        for (int k = 0; k < 64;  k++) acc += shs[k]*g_s2s_whh_t[k*256+tid];
        sg[tid] = acc;
        __syncthreads();
        if (tid < 64) {
            float iv = sg[tid], fv = sg[64+tid], gv = sg[128+tid], ov = sg[192+tid];
            float c = sigf(fv)*scs[tid] + sigf(iv)*tanhf(gv);
            scs[tid] = c;
            shs[tid] = sigf(ov)*tanhf(c);
        }
        __syncthreads();
        if (tid < 64) {
            float a = 0.f;
            #pragma unroll 8
            for (int k = 0; k < 64; k++) a += so[tid*65+k]*shs[k];
            se[tid] = a;
        }
        __syncthreads();
        if (tid < 32) {
            float m1 = fmaxf(se[tid], se[tid+32]);
            #pragma unroll
            for (int off = 16; off; off >>= 1) m1 = fmaxf(m1, __shfl_xor_sync(0xffffffffu, m1, off));
            if (tid == 0) sred[0] = m1;
        }
        __syncthreads();
        if (tid < 64) se[tid] = expf(se[tid] - sred[0]);
        __syncthreads();
        if (tid < 32) {
            float s1 = se[tid] + se[tid+32];
            #pragma unroll
            for (int off = 16; off; off >>= 1) s1 += __shfl_xor_sync(0xffffffffu, s1, off);
            if (tid == 0) sred[1] = s1;
        }
        __syncthreads();
        if (tid < 64) {
            float inv = 1.f/sred[1];
            float racc = 0.f;
            #pragma unroll 8
            for (int n = 0; n < 64; n++) racc += se[n]*so[n*65+tid];
            sq[64+tid] = racc*inv;
            sq[tid] = shs[tid];
        }
        __syncthreads();
    }
    float acc = mem_bih[tid] + mem_bhh[tid];
    #pragma unroll 4
    for (int k = 0; k < 128; k++) acc += sq[k]*g_mem_wih_t[k*256+tid];
    sg[tid] = acc;
    __syncthreads();
    if (tid < 64) {
        float iv = sg[tid], gv = sg[128+tid], ov = sg[192+tid];
        float cx = sigf(iv)*tanhf(gv);
        float hx = sigf(ov)*tanhf(cx);
        g_hx[g*64+tid] = hx;
        if (out_size >= NT*6 + 2*NG*D) {
            d_out[NT*6 + g*64 + tid]        = hx;
            d_out[NT*6 + NG*D + g*64 + tid] = cx;
        }
    }
}

// head
__global__ void __launch_bounds__(64)
k_final(const int* __restrict__ nonring, const int* __restrict__ nrbidx,
        const float* __restrict__ lin1_b, const float* __restrict__ lin2_w,
        const float* __restrict__ lin2_b, float* __restrict__ d_out)
{
    __shared__ float sf[320];
    __shared__ float so1[64];
    int r = blockIdx.x, tid = threadIdx.x;
    int ch = r / 48;
    int t  = (r % 48) * 64 + tid;
    sf[tid*5 + 0] = g_hx[nrbidx[t]*64 + ch];
    #pragma unroll
    for (int s = 1; s < 5; s++) {
        int node = nonring[(s-1)*NT + t];
        sf[tid*5 + s] = g_out[node*64 + ch];
    }
    __syncthreads();
    float acc = lin1_b[tid];
    #pragma unroll 8
    for (int q = 0; q < 320; q++) acc += sf[q]*g_lin1_t[q*64+tid];
    so1[tid] = fmaxf(acc, 0.f);
    __syncthreads();
    if (tid < 6) {
        float a2 = lin2_b[tid];
        #pragma unroll 8
        for (int k = 0; k < 64; k++) a2 += so1[k]*lin2_w[tid*64+k];
        d_out[r*6 + tid] = a2;
    }
}

extern "C" void kernel_launch(void* const* d_in, const int* in_sizes, int n_in,
                              void* d_out, int out_size)
{
    const float* x        = (const float*)d_in[0];
    const float* ea       = (const float*)d_in[1];
    const int*   eidx     = (const int*)  d_in[2];
    const int*   nonring  = (const int*)  d_in[4];
    const int*   nrbidx   = (const int*)  d_in[5];
    int base = (n_in >= 32) ? 8 : 6;
    const float* lin0_w  = (const float*)d_in[base+0];
    const float* lin0_b  = (const float*)d_in[base+1];
    const float* e1_w    = (const float*)d_in[base+2];
    const float* e1_b    = (const float*)d_in[base+3];
    const float* e2_w    = (const float*)d_in[base+4];
    const float* e2_b    = (const float*)d_in[base+5];
    const float* root_w  = (const float*)d_in[base+6];
    const float* conv_b  = (const float*)d_in[base+7];
    const float* gru_wih = (const float*)d_in[base+8];
    const float* gru_whh = (const float*)d_in[base+9];
    const float* gru_bih = (const float*)d_in[base+10];
    const float* gru_bhh = (const float*)d_in[base+11];
    const float* s2s_wih = (const float*)d_in[base+12];
    const float* s2s_whh = (const float*)d_in[base+13];
    const float* s2s_bih = (const float*)d_in[base+14];
    const float* s2s_bhh = (const float*)d_in[base+15];
    const float* mem_wih = (const float*)d_in[base+16];
    const float* mem_bih = (const float*)d_in[base+18];
    const float* mem_bhh = (const float*)d_in[base+19];
    const float* lin1_w  = (const float*)d_in[base+20];
    const float* lin1_b  = (const float*)d_in[base+21];
    const float* lin2_w  = (const float*)d_in[base+22];
    const float* lin2_b  = (const float*)d_in[base+23];
    float* out = (float*)d_out;

    const int* src = eidx;
    const int* dst = eidx + N_EDGES;

    const int BUILD_SMEM = 256 * ROWB;       // 102400 bytes
    const int GIH_SMEM   = 192 * ROWB;       // 76800 bytes
    const int SCAN_SMEM  = 2 * N_NODES * 4;  // 131072 bytes
    static int smem_set = 0;
    if (!smem_set) {
        cudaFuncSetAttribute(k_build_ew, cudaFuncAttributeMaxDynamicSharedMemorySize, BUILD_SMEM);
        cudaFuncSetAttribute(k_gih_h,    cudaFuncAttributeMaxDynamicSharedMemorySize, GIH_SMEM);
        cudaFuncSetAttribute(k_scanfill, cudaFuncAttributeMaxDynamicSharedMemorySize, SCAN_SMEM);
        smem_set = 1;
    }

    k_prep_all<<<(N_EDGES*D)/256, 256>>>(gru_wih, gru_whh, s2s_wih, s2s_whh, mem_wih,
                                         lin1_w, e2_w, x, lin0_w, lin0_b, ea, e1_w, e1_b);
    k_count<<<N_EDGES/256, 256>>>(dst);
    k_scanfill<<<1, 1024, SCAN_SMEM>>>(dst);
    k_build_ew<<<dim3(N_EDGES/128, 4096/128), 128, BUILD_SMEM>>>(e2_b);   // launch #4 (profiled)

    for (int it = 0; it < 6; it++) {
        k_msg_w<<<N_EDGES/8, 256>>>(src);
        k_gemm1<<<N_NODES/64, 256>>>(root_w, conv_b);
        k_gih_h<<<dim3(N_NODES/128, 3, 2), 128, GIH_SMEM>>>(gru_bih, gru_bhh);
        k_gru<<<(N_NODES*D)/256, 256>>>();
    }

    k_s2s<<<NG, 256>>>(s2s_bih, s2s_bhh, mem_bih, mem_bhh, out, out_size);
    k_final<<<NT, 64>>>(nonring, nrbidx, lin1_b, lin2_w, lin2_b, out);
}

// round 15
// speedup vs baseline: 1.2820x; 1.2820x over previous
#include <cuda_runtime.h>
#include <cuda_fp16.h>
#include <cuda_bf16.h>
#include <math.h>
#include <stdint.h>

#define N_NODES 16384
#define N_EDGES 32768
#define NG 256
#define TPG 12
#define NT (NG*TPG)
#define D 64
#define BK 192          // split-bf16 K extent (3 x 64)

__device__ float  g_out[N_NODES*D];
__device__ __nv_bfloat16 g_outb[(size_t)N_NODES*BK];   // split-bf16 of out/h  [hi|lo|hi]
__device__ __nv_bfloat16 g_mb  [(size_t)N_NODES*BK];   // split-bf16 of m      [hi|lo|hi]
__device__ __nv_bfloat16 g_heb[(size_t)N_EDGES*BK];
__device__ __nv_bfloat16 g_w2b[4096*BK];
__device__ __nv_bfloat16 g_wihb[192*BK];               // split-B [hi|hi|lo]
__device__ __nv_bfloat16 g_whhb[192*BK];
__device__ __half g_ew [(size_t)N_EDGES*D*D];
__device__ float  g_msg[(size_t)N_EDGES*D];            // indexed by edge id (sequential ew stream)
__device__ float  g_gi [N_NODES*3*D];
__device__ float  g_gh [N_NODES*3*D];
__device__ int    g_cnt[N_NODES];
__device__ int    g_eoff[N_NODES+1];
__device__ int    g_eid[N_EDGES];
__device__ float  g_s2s_wih_t[2*D*4*D];
__device__ float  g_s2s_whh_t[D*4*D];
__device__ float  g_mem_wih_t[2*D*4*D];
__device__ float  g_lin1_t[5*D*D];
__device__ float  g_hx[NG*D];

__device__ __forceinline__ float sigf(float x) { return 1.0f/(1.0f+expf(-x)); }

__device__ __forceinline__ uint32_t smem_to_u32(const void* p) {
    uint32_t a;
    asm("{ .reg .u64 t; cvta.to.shared.u64 t, %1; cvt.u32.u64 %0, t; }" : "=r"(a) : "l"(p));
    return a;
}

// ---------------- merged prologue ----------------
__global__ void k_prep_all(const float* __restrict__ gru_wih, const float* __restrict__ gru_whh,
                           const float* __restrict__ s2s_wih, const float* __restrict__ s2s_whh,
                           const float* __restrict__ mem_wih, const float* __restrict__ lin1_w,
                           const float* __restrict__ e2_w,
                           const float* __restrict__ x, const float* __restrict__ lin0_w,
                           const float* __restrict__ lin0_b,
                           const float* __restrict__ ea, const float* __restrict__ e1_w,
                           const float* __restrict__ e1_b)
{
    int i = blockIdx.x*blockDim.x + threadIdx.x;
    if (i < 4096*64) {
        int n = i >> 6, k = i & 63;
        float v = e2_w[i];
        __nv_bfloat16 hi = __float2bfloat16(v);
        __nv_bfloat16 lo = __float2bfloat16(v - __bfloat162float(hi));
        g_w2b[n*BK + k]       = hi;
        g_w2b[n*BK + 64 + k]  = hi;
        g_w2b[n*BK + 128 + k] = lo;
    }
    if (i < 192*64) {
        int j = i >> 6, k = i & 63;
        float wv = gru_wih[i];
        __nv_bfloat16 hi = __float2bfloat16(wv);
        __nv_bfloat16 lo = __float2bfloat16(wv - __bfloat162float(hi));
        g_wihb[j*BK + k]       = hi;
        g_wihb[j*BK + 64 + k]  = hi;
        g_wihb[j*BK + 128 + k] = lo;
        float wh = gru_whh[i];
        __nv_bfloat16 hh = __float2bfloat16(wh);
        __nv_bfloat16 hl = __float2bfloat16(wh - __bfloat162float(hh));
        g_whhb[j*BK + k]       = hh;
        g_whhb[j*BK + 64 + k]  = hh;
        g_whhb[j*BK + 128 + k] = hl;
    }
    if (i < 128*256) { int k = i/256,  j = i%256;  g_s2s_wih_t[i] = s2s_wih[j*128+k];
                                                   g_mem_wih_t[i] = mem_wih[j*128+k]; }
    if (i < 64*256)  { int k = i/256,  j = i%256;  g_s2s_whh_t[i] = s2s_whh[j*64+k]; }
    if (i < 320*64)  { int q = i/64,   j = i%64;   g_lin1_t[i] = lin1_w[j*320+q]; }
    if (i < N_NODES) g_cnt[i] = 0;
    if (i < N_NODES*D) {
        int n = i >> 6, j = i & 63;
        float acc = lin0_b[j];
        #pragma unroll
        for (int k = 0; k < 3; k++) acc += x[n*3+k]*lin0_w[j*3+k];
        float v = fmaxf(acc, 0.f);
        g_out[i] = v;
        __nv_bfloat16 hi = __float2bfloat16(v);
        __nv_bfloat16 lo = __float2bfloat16(v - __bfloat162float(hi));
        size_t base = (size_t)n*BK;
        g_outb[base + j]       = hi;
        g_outb[base + 64 + j]  = lo;
        g_outb[base + 128 + j] = hi;
    }
    if (i < N_EDGES*D) {
        int e = i >> 6, j = i & 63;
        float acc = e1_b[j];
        #pragma unroll
        for (int k = 0; k < 6; k++) acc += ea[e*6+k]*e1_w[j*6+k];
        float v = fmaxf(acc, 0.f);
        __nv_bfloat16 hi = __float2bfloat16(v);
        __nv_bfloat16 lo = __float2bfloat16(v - __bfloat162float(hi));
        size_t base = (size_t)e*BK;
        g_heb[base + j]       = hi;
        g_heb[base + 64 + j]  = lo;
        g_heb[base + 128 + j] = hi;
    }
}

// ---------------- HMMA primitives ----------------
__device__ __forceinline__ void mma16816(float c[4], uint32_t a0, uint32_t a1, uint32_t a2, uint32_t a3,
                                         uint32_t b0, uint32_t b1)
{
    asm volatile(
        "mma.sync.aligned.m16n8k16.row.col.f32.bf16.bf16.f32 "
        "{%0,%1,%2,%3}, {%4,%5,%6,%7}, {%8,%9}, {%0,%1,%2,%3};"
        : "+f"(c[0]), "+f"(c[1]), "+f"(c[2]), "+f"(c[3])
        : "r"(a0), "r"(a1), "r"(a2), "r"(a3), "r"(b0), "r"(b1));
}

#define ROWB 400   // bytes per smem row: 4-bank shift/row -> LDSM conflict-free
#define CPITCH 136 // C-stage pitch in halfs

// ---------------- build of g_ew (HMMA plateau ~121 T-MAC/s) ----------------
__global__ void __launch_bounds__(128)
k_build_ew(const float* __restrict__ e2_b)
{
    extern __shared__ char smem[];
    char* sA = smem;
    char* sB = smem + 128*ROWB;
    uint32_t sab = smem_to_u32(smem);
    int tid = threadIdx.x;
    int wid = tid >> 5, lane = tid & 31;
    int e0 = blockIdx.x * 128;
    int n0 = blockIdx.y * 128;

    for (int idx = tid; idx < 128*24; idx += 128) {
        int row = idx / 24, c = idx % 24;
        *(uint4*)(sA + row*ROWB + c*16) = ((const uint4*)(g_heb + (size_t)(e0+row)*BK))[c];
        *(uint4*)(sB + row*ROWB + c*16) = ((const uint4*)(g_w2b + (size_t)(n0+row)*BK))[c];
    }
    __syncthreads();

    int wm = (wid & 1) * 64;
    int wn = (wid >> 1) * 64;
    int grp = lane >> 3;
    int l7  = lane & 7;
    uint32_t aoff = sab + (uint32_t)((wm + (grp & 1)*8 + l7)*ROWB + ((grp >> 1)*8)*2);
    uint32_t boff = sab + (uint32_t)(128*ROWB + (wn + (grp >> 1)*8 + l7)*ROWB + ((grp & 1)*8)*2);

    float acc[4][8][4] = {};
    #pragma unroll
    for (int ks = 0; ks < 12; ks++) {
        uint32_t kb2 = ks * 32;
        uint32_t af[4][4];
        #pragma unroll
        for (int mt = 0; mt < 4; mt++) {
            asm volatile("ldmatrix.sync.aligned.m8n8.x4.shared.b16 {%0,%1,%2,%3}, [%4];"
                : "=r"(af[mt][0]), "=r"(af[mt][1]), "=r"(af[mt][2]), "=r"(af[mt][3])
                : "r"(aoff + mt*16*ROWB + kb2));
        }
        uint32_t bf[8][2];
        #pragma unroll
        for (int np = 0; np < 4; np++) {
            uint32_t r0, r1, r2, r3;
            asm volatile("ldmatrix.sync.aligned.m8n8.x4.shared.b16 {%0,%1,%2,%3}, [%4];"
                : "=r"(r0), "=r"(r1), "=r"(r2), "=r"(r3)
                : "r"(boff + np*16*ROWB + kb2));
            bf[np*2][0] = r0; bf[np*2][1] = r1;
            bf[np*2+1][0] = r2; bf[np*2+1][1] = r3;
        }
        #pragma unroll
        for (int mt = 0; mt < 4; mt++)
            #pragma unroll
            for (int nt = 0; nt < 8; nt++)
                mma16816(acc[mt][nt], af[mt][0], af[mt][1], af[mt][2], af[mt][3],
                         bf[nt][0], bf[nt][1]);
    }

    __syncthreads();
    __half* sC = (__half*)smem;
    int gr = lane >> 2;
    int cc = (lane & 3) * 2;
    #pragma unroll
    for (int nt = 0; nt < 8; nt++) {
        int col = wn + nt*8 + cc;
        float b0v = e2_b[n0 + col], b1v = e2_b[n0 + col + 1];
        #pragma unroll
        for (int mt = 0; mt < 4; mt++) {
            int r0 = wm + mt*16 + gr;
            *(__half2*)(sC + r0*CPITCH + col) =
                __floats2half2_rn(acc[mt][nt][0] + b0v, acc[mt][nt][1] + b1v);
            *(__half2*)(sC + (r0+8)*CPITCH + col) =
                __floats2half2_rn(acc[mt][nt][2] + b0v, acc[mt][nt][3] + b1v);
        }
    }
    __syncthreads();
    for (int idx = tid; idx < 128*16; idx += 128) {
        int row = idx >> 4, ch = idx & 15;
        uint4 v = *(const uint4*)(sC + row*CPITCH + ch*8);
        *(uint4*)(g_ew + (size_t)(e0+row)*4096 + n0 + ch*8) = v;
    }
}

// ---------------- HMMA gi/gh: grid (128, 3, 2) ----------
__global__ void __launch_bounds__(128)
k_gih_h(const float* __restrict__ bih, const float* __restrict__ bhh)
{
    extern __shared__ char smem[];
    char* sA = smem;
    char* sB = smem + 128*ROWB;
    uint32_t sab = smem_to_u32(smem);
    int tid = threadIdx.x;
    int wid = tid >> 5, lane = tid & 31;
    int e0 = blockIdx.x * 128;
    int j0 = blockIdx.y * 64;
    int half = blockIdx.z;
    const __nv_bfloat16* A = half ? g_outb : g_mb;
    const __nv_bfloat16* B = half ? g_whhb : g_wihb;
    const float* bias = half ? bhh : bih;
    float* C = half ? g_gh : g_gi;

    for (int idx = tid; idx < 128*24; idx += 128) {
        int row = idx / 24, c = idx % 24;
        *(uint4*)(sA + row*ROWB + c*16) = ((const uint4*)(A + (size_t)(e0+row)*BK))[c];
    }
    for (int idx = tid; idx < 64*24; idx += 128) {
        int row = idx / 24, c = idx % 24;
        *(uint4*)(sB + row*ROWB + c*16) = ((const uint4*)(B + (size_t)(j0+row)*BK))[c];
    }
    __syncthreads();

    int wm = (wid & 1) * 64;
    int wn = (wid >> 1) * 32;
    int grp = lane >> 3;
    int l7  = lane & 7;
    uint32_t aoff = sab + (uint32_t)((wm + (grp & 1)*8 + l7)*ROWB + ((grp >> 1)*8)*2);
    uint32_t boff = sab + (uint32_t)(128*ROWB + (wn + (grp >> 1)*8 + l7)*ROWB + ((grp & 1)*8)*2);

    float acc[4][4][4] = {};
    #pragma unroll
    for (int ks = 0; ks < 12; ks++) {
        uint32_t kb2 = ks * 32;
        uint32_t af[4][4];
        #pragma unroll
        for (int mt = 0; mt < 4; mt++) {
            asm volatile("ldmatrix.sync.aligned.m8n8.x4.shared.b16 {%0,%1,%2,%3}, [%4];"
                : "=r"(af[mt][0]), "=r"(af[mt][1]), "=r"(af[mt][2]), "=r"(af[mt][3])
                : "r"(aoff + mt*16*ROWB + kb2));
        }
        uint32_t bf[4][2];
        #pragma unroll
        for (int np = 0; np < 2; np++) {
            uint32_t r0, r1, r2, r3;
            asm volatile("ldmatrix.sync.aligned.m8n8.x4.shared.b16 {%0,%1,%2,%3}, [%4];"
                : "=r"(r0), "=r"(r1), "=r"(r2), "=r"(r3)
                : "r"(boff + np*16*ROWB + kb2));
            bf[np*2][0] = r0; bf[np*2][1] = r1;
            bf[np*2+1][0] = r2; bf[np*2+1][1] = r3;
        }
        #pragma unroll
        for (int mt = 0; mt < 4; mt++)
            #pragma unroll
            for (int nt = 0; nt < 4; nt++)
                mma16816(acc[mt][nt], af[mt][0], af[mt][1], af[mt][2], af[mt][3],
                         bf[nt][0], bf[nt][1]);
    }

    int gr = lane >> 2;
    int cc = (lane & 3) * 2;
    #pragma unroll
    for (int nt = 0; nt < 4; nt++) {
        int col = j0 + wn + nt*8 + cc;
        float b0v = bias[col], b1v = bias[col+1];
        #pragma unroll
        for (int mt = 0; mt < 4; mt++) {
            int r0 = e0 + wm + mt*16 + gr;
            *(float2*)(C + (size_t)r0*192 + col) =
                make_float2(acc[mt][nt][0] + b0v, acc[mt][nt][1] + b1v);
            *(float2*)(C + (size_t)(r0+8)*192 + col) =
                make_float2(acc[mt][nt][2] + b0v, acc[mt][nt][3] + b1v);
        }
    }
}

// ---------------- CSR build ----------------
__global__ void k_count(const int* __restrict__ dst)
{
    int e = blockIdx.x*blockDim.x + threadIdx.x;
    if (e < N_EDGES) atomicAdd(&g_cnt[dst[e]], 1);
}

// merged scan + fill (one block; smem offsets + counters)
__global__ void __launch_bounds__(1024) k_scanfill(const int* __restrict__ dst)
{
    extern __shared__ int sm[];               // [0:16384) eoff base, [16384:32768) cur
    int* seoff = sm;
    int* scur  = sm + N_NODES;
    __shared__ int part[1024];
    int tid = threadIdx.x;
    int base = tid*16;
    int loc[16]; int tsum = 0;
    #pragma unroll
    for (int t = 0; t < 16; t++) { loc[t] = g_cnt[base+t]; tsum += loc[t]; }
    part[tid] = tsum;
    __syncthreads();
    for (int d = 1; d < 1024; d <<= 1) {
        int v = 0;
        if (tid >= d) v = part[tid-d];
        __syncthreads();
        if (tid >= d) part[tid] += v;
        __syncthreads();
    }
    int run = part[tid] - tsum;
    #pragma unroll
    for (int t = 0; t < 16; t++) {
        seoff[base+t] = run;
        g_eoff[base+t] = run;
        scur[base+t] = 0;
        run += loc[t];
    }
    if (tid == 1023) g_eoff[N_NODES] = part[1023];
    __syncthreads();
    for (int e = tid; e < N_EDGES; e += 1024) {
        int d = dst[e];
        int p = atomicAdd(&scur[d], 1);
        g_eid[seoff[d] + p] = e;
    }
}

// ---------------- msg: sequential ew stream (DRAM floor: 80% @ 6.3 TB/s) ----------------
__global__ void __launch_bounds__(256)
k_msg_w(const int* __restrict__ src)
{
    __shared__ float s_o[8][64];
    int w = threadIdx.x >> 5;
    int lane = threadIdx.x & 31;
    int e = blockIdx.x*8 + w;
    int s = src[e];
    s_o[w][lane]      = g_out[s*64 + lane];
    s_o[w][lane + 32] = g_out[s*64 + 32 + lane];
    __syncwarp();
    int rgrp = lane >> 3;
    float acc[8] = {};
    const uint4* ew4 = (const uint4*)(g_ew + (size_t)e*4096);
    #pragma unroll
    for (int i = 0; i < 16; i++) {
        int row = i*4 + rgrp;
        uint4 v = ew4[i*32 + lane];
        float a = s_o[w][row];
        const __half2* hp = (const __half2*)&v;
        #pragma unroll
        for (int q = 0; q < 4; q++) {
            float2 f = __half22float2(hp[q]);
            acc[2*q]   += a*f.x;
            acc[2*q+1] += a*f.y;
        }
    }
    #pragma unroll
    for (int q = 0; q < 8; q++) {
        acc[q] += __shfl_xor_sync(0xffffffffu, acc[q], 8);
        acc[q] += __shfl_xor_sync(0xffffffffu, acc[q], 16);
    }
    if (lane < 8) {
        float4* op = (float4*)(g_msg + (size_t)e*64 + lane*8);
        op[0] = make_float4(acc[0], acc[1], acc[2], acc[3]);
        op[1] = make_float4(acc[4], acc[5], acc[6], acc[7]);
    }
}

// ---------------- node GEMM + CSR-mean (g_eid gather); writes split-bf16 g_mb ----------------
__global__ void __launch_bounds__(256)
k_gemm1(const float* __restrict__ Bext, const float* __restrict__ bias)
{
    __shared__ __align__(16) float sAt[64][68];
    __shared__ __align__(16) float sB[64][64];
    int tid = threadIdx.x;
    int e0 = blockIdx.x * 64;
    for (int l = tid; l < 64*64; l += 256) {
        int r = l >> 6, c = l & 63;
        sAt[c][r] = g_out[(e0 + r)*64 + c];
        sB[r][c]  = Bext[r*64 + c];
    }
    __syncthreads();
    int te = (tid >> 4) << 2;
    int tj = (tid & 15) << 2;
    float acc[4][4] = {};
    #pragma unroll
    for (int k = 0; k < 64; k++) {
        float4 a = *(const float4*)&sAt[k][te];
        float4 b = *(const float4*)&sB[k][tj];
        acc[0][0] += a.x*b.x; acc[0][1] += a.x*b.y; acc[0][2] += a.x*b.z; acc[0][3] += a.x*b.w;
        acc[1][0] += a.y*b.x; acc[1][1] += a.y*b.y; acc[1][2] += a.y*b.z; acc[1][3] += a.y*b.w;
        acc[2][0] += a.z*b.x; acc[2][1] += a.z*b.y; acc[2][2] += a.z*b.z; acc[2][3] += a.z*b.w;
        acc[3][0] += a.w*b.x; acc[3][1] += a.w*b.y; acc[3][2] += a.w*b.z; acc[3][3] += a.w*b.w;
    }
    #pragma unroll
    for (int ii = 0; ii < 4; ii++) {
        int row = e0 + te + ii;
        int b0 = g_eoff[row], b1 = g_eoff[row+1];
        float s0 = 0.f, s1 = 0.f, s2 = 0.f, s3 = 0.f;
        for (int p = b0; p < b1; p++) {
            int e = g_eid[p];
            float4 v = *(const float4*)(g_msg + (size_t)e*64 + tj);
            s0 += v.x; s1 += v.y; s2 += v.z; s3 += v.w;
        }
        float inv = 1.0f/fmaxf((float)(b1 - b0), 1.f);
        float vals[4] = { fmaxf(acc[ii][0] + s0*inv + bias[tj+0], 0.f),
                          fmaxf(acc[ii][1] + s1*inv + bias[tj+1], 0.f),
                          fmaxf(acc[ii][2] + s2*inv + bias[tj+2], 0.f),
                          fmaxf(acc[ii][3] + s3*inv + bias[tj+3], 0.f) };
        size_t base = (size_t)row*BK;
        #pragma unroll
        for (int jj = 0; jj < 4; jj++) {
            float v = vals[jj];
            __nv_bfloat16 hi = __float2bfloat16(v);
            __nv_bfloat16 lo = __float2bfloat16(v - __bfloat162float(hi));
            g_mb[base + tj + jj]        = hi;
            g_mb[base + 64 + tj + jj]   = lo;
            g_mb[base + 128 + tj + jj]  = hi;
        }
    }
}

__global__ void k_gru()
{
    int i = blockIdx.x*blockDim.x + threadIdx.x;
    int n = i >> 6, j = i & 63;
    const float* gi = g_gi + n*192;
    const float* gh = g_gh + n*192;
    float r  = sigf(gi[j]      + gh[j]);
    float z  = sigf(gi[64+j]   + gh[64+j]);
    float nn = tanhf(gi[128+j] + r*gh[128+j]);
    float h  = g_out[i];
    float hn = (1.f - z)*nn + z*h;
    g_out[i] = hn;
    __nv_bfloat16 hi = __float2bfloat16(hn);
    __nv_bfloat16 lo = __float2bfloat16(hn - __bfloat162float(hi));
    size_t base = (size_t)n*BK;
    g_outb[base + j]       = hi;
    g_outb[base + 64 + j]  = lo;
    g_outb[base + 128 + j] = hi;
}

// Set2Set (6 steps) + memory LSTM; one block per graph
__global__ void __launch_bounds__(256)
k_s2s(const float* __restrict__ s2s_bih, const float* __restrict__ s2s_bhh,
      const float* __restrict__ mem_bih, const float* __restrict__ mem_bhh,
      float* __restrict__ d_out, int out_size)
{
    __shared__ float so[64*65];
    __shared__ float sq[128];
    __shared__ float shs[64], scs[64], sg[256], se[64];
    __shared__ float sred[2];
    int g = blockIdx.x, tid = threadIdx.x;
    for (int l = tid; l < 64*64; l += 256) {
        int n = l >> 6, c = l & 63;
        so[n*65+c] = g_out[(g*64+n)*64 + c];
    }
    if (tid < 128) sq[tid] = 0.f;
    if (tid < 64) { shs[tid] = 0.f; scs[tid] = 0.f; }
    __syncthreads();
    for (int step = 0; step < 6; step++) {
        float acc = s2s_bih[tid] + s2s_bhh[tid];
        #pragma unroll 4
        for (int k = 0; k < 128; k++) acc += sq[k]*g_s2s_wih_t[k*256+tid];
        #pragma unroll 4
        for (int k = 0; k < 64;  k++) acc += shs[k]*g_s2s_whh_t[k*256+tid];
        sg[tid] = acc;
        __syncthreads();
        if (tid < 64) {
            float iv = sg[tid], fv = sg[64+tid], gv = sg[128+tid], ov = sg[192+tid];
            float c = sigf(fv)*scs[tid] + sigf(iv)*tanhf(gv);
            scs[tid] = c;
            shs[tid] = sigf(ov)*tanhf(c);
        }
        __syncthreads();
        if (tid < 64) {
            float a = 0.f;
            #pragma unroll 8
            for (int k = 0; k < 64; k++) a += so[tid*65+k]*shs[k];
            se[tid] = a;
        }
        __syncthreads();
        if (tid < 32) {
            float m1 = fmaxf(se[tid], se[tid+32]);
            #pragma unroll
            for (int off = 16; off; off >>= 1) m1 = fmaxf(m1, __shfl_xor_sync(0xffffffffu, m1, off));
            if (tid == 0) sred[0] = m1;
        }
        __syncthreads();
        if (tid < 64) se[tid] = expf(se[tid] - sred[0]);
        __syncthreads();
        if (tid < 32) {
            float s1 = se[tid] + se[tid+32];
            #pragma unroll
            for (int off = 16; off; off >>= 1) s1 += __shfl_xor_sync(0xffffffffu, s1, off);
            if (tid == 0) sred[1] = s1;
        }
        __syncthreads();
        if (tid < 64) {
            float inv = 1.f/sred[1];
            float racc = 0.f;
            #pragma unroll 8
            for (int n = 0; n < 64; n++) racc += se[n]*so[n*65+tid];
            sq[64+tid] = racc*inv;
            sq[tid] = shs[tid];
        }
        __syncthreads();
    }
    float acc = mem_bih[tid] + mem_bhh[tid];
    #pragma unroll 4
    for (int k = 0; k < 128; k++) acc += sq[k]*g_mem_wih_t[k*256+tid];
    sg[tid] = acc;
    __syncthreads();
    if (tid < 64) {
        float iv = sg[tid], gv = sg[128+tid], ov = sg[192+tid];
        float cx = sigf(iv)*tanhf(gv);
        float hx = sigf(ov)*tanhf(cx);
        g_hx[g*64+tid] = hx;
        if (out_size >= NT*6 + 2*NG*D) {
            d_out[NT*6 + g*64 + tid]        = hx;
            d_out[NT*6 + NG*D + g*64 + tid] = cx;
        }
    }
}

// head
__global__ void __launch_bounds__(64)
k_final(const int* __restrict__ nonring, const int* __restrict__ nrbidx,
        const float* __restrict__ lin1_b, const float* __restrict__ lin2_w,
        const float* __restrict__ lin2_b, float* __restrict__ d_out)
{
    __shared__ float sf[320];
    __shared__ float so1[64];
    int r = blockIdx.x, tid = threadIdx.x;
    int ch = r / 48;
    int t  = (r % 48) * 64 + tid;
    sf[tid*5 + 0] = g_hx[nrbidx[t]*64 + ch];
    #pragma unroll
    for (int s = 1; s < 5; s++) {
        int node = nonring[(s-1)*NT + t];
        sf[tid*5 + s] = g_out[node*64 + ch];
    }
    __syncthreads();
    float acc = lin1_b[tid];
    #pragma unroll 8
    for (int q = 0; q < 320; q++) acc += sf[q]*g_lin1_t[q*64+tid];
    so1[tid] = fmaxf(acc, 0.f);
    __syncthreads();
    if (tid < 6) {
        float a2 = lin2_b[tid];
        #pragma unroll 8
        for (int k = 0; k < 64; k++) a2 += so1[k]*lin2_w[tid*64+k];
        d_out[r*6 + tid] = a2;
    }
}

extern "C" void kernel_launch(void* const* d_in, const int* in_sizes, int n_in,
                              void* d_out, int out_size)
{
    const float* x        = (const float*)d_in[0];
    const float* ea       = (const float*)d_in[1];
    const int*   eidx     = (const int*)  d_in[2];
    const int*   nonring  = (const int*)  d_in[4];
    const int*   nrbidx   = (const int*)  d_in[5];
    int base = (n_in >= 32) ? 8 : 6;
    const float* lin0_w  = (const float*)d_in[base+0];
    const float* lin0_b  = (const float*)d_in[base+1];
    const float* e1_w    = (const float*)d_in[base+2];
    const float* e1_b    = (const float*)d_in[base+3];
    const float* e2_w    = (const float*)d_in[base+4];
    const float* e2_b    = (const float*)d_in[base+5];
    const float* root_w  = (const float*)d_in[base+6];
    const float* conv_b  = (const float*)d_in[base+7];
    const float* gru_wih = (const float*)d_in[base+8];
    const float* gru_whh = (const float*)d_in[base+9];
    const float* gru_bih = (const float*)d_in[base+10];
    const float* gru_bhh = (const float*)d_in[base+11];
    const float* s2s_wih = (const float*)d_in[base+12];
    const float* s2s_whh = (const float*)d_in[base+13];
    const float* s2s_bih = (const float*)d_in[base+14];
    const float* s2s_bhh = (const float*)d_in[base+15];
    const float* mem_wih = (const float*)d_in[base+16];
    const float* mem_bih = (const float*)d_in[base+18];
    const float* mem_bhh = (const float*)d_in[base+19];
    const float* lin1_w  = (const float*)d_in[base+20];
    const float* lin1_b  = (const float*)d_in[base+21];
    const float* lin2_w  = (const float*)d_in[base+22];
    const float* lin2_b  = (const float*)d_in[base+23];
    float* out = (float*)d_out;

    const int* src = eidx;
    const int* dst = eidx + N_EDGES;

    const int BUILD_SMEM = 256 * ROWB;       // 102400 bytes
    const int GIH_SMEM   = 192 * ROWB;       // 76800 bytes
    const int SCAN_SMEM  = 2 * N_NODES * 4;  // 131072 bytes
    static int smem_set = 0;
    if (!smem_set) {
        cudaFuncSetAttribute(k_build_ew, cudaFuncAttributeMaxDynamicSharedMemorySize, BUILD_SMEM);
        cudaFuncSetAttribute(k_gih_h,    cudaFuncAttributeMaxDynamicSharedMemorySize, GIH_SMEM);
        cudaFuncSetAttribute(k_scanfill, cudaFuncAttributeMaxDynamicSharedMemorySize, SCAN_SMEM);
        smem_set = 1;
    }

    k_prep_all<<<(N_EDGES*D)/256, 256>>>(gru_wih, gru_whh, s2s_wih, s2s_whh, mem_wih,
                                         lin1_w, e2_w, x, lin0_w, lin0_b, ea, e1_w, e1_b);
    k_count<<<N_EDGES/256, 256>>>(dst);
    k_scanfill<<<1, 1024, SCAN_SMEM>>>(dst);
    k_build_ew<<<dim3(N_EDGES/128, 4096/128), 128, BUILD_SMEM>>>(e2_b);   // launch #4 (profiled)

    for (int it = 0; it < 6; it++) {
        k_msg_w<<<N_EDGES/8, 256>>>(src);
        k_gemm1<<<N_NODES/64, 256>>>(root_w, conv_b);
        k_gih_h<<<dim3(N_NODES/128, 3, 2), 128, GIH_SMEM>>>(gru_bih, gru_bhh);
        k_gru<<<(N_NODES*D)/256, 256>>>();
    }

    k_s2s<<<NG, 256>>>(s2s_bih, s2s_bhh, mem_bih, mem_bhh, out, out_size);
    k_final<<<NT, 64>>>(nonring, nrbidx, lin1_b, lin2_w, lin2_b, out);
}

// round 16
// speedup vs baseline: 1.4463x; 1.1282x over previous
#include <cuda_runtime.h>
#include <cuda_fp16.h>
#include <cuda_bf16.h>
#include <math.h>
#include <stdint.h>

#define N_NODES 16384
#define N_EDGES 32768
#define NG 256
#define TPG 12
#define NT (NG*TPG)
#define D 64
#define BK 192          // split-bf16 K extent (3 x 64)

__device__ float  g_out[N_NODES*D];
__device__ __nv_bfloat16 g_outb[(size_t)N_NODES*BK];   // split-bf16 of out/h  [hi|lo|hi]
__device__ __nv_bfloat16 g_mb  [(size_t)N_NODES*BK];   // split-bf16 of m      [hi|lo|hi]
__device__ __nv_bfloat16 g_heb[(size_t)N_EDGES*BK];
__device__ __nv_bfloat16 g_w2b[4096*BK];
__device__ __nv_bfloat16 g_wihb[192*BK];               // split-B [hi|hi|lo]
__device__ __nv_bfloat16 g_whhb[192*BK];
__device__ __half g_ew [(size_t)N_EDGES*D*D];
__device__ float  g_msg[(size_t)N_EDGES*D];            // indexed by edge id (sequential ew stream)
__device__ float  g_gi [N_NODES*3*D];
__device__ float  g_gh [N_NODES*3*D];
__device__ int    g_cnt[N_NODES];
__device__ int    g_cur[N_NODES];
__device__ int    g_eoff[N_NODES+1];
__device__ int    g_eid[N_EDGES];
__device__ float  g_s2s_wih_t[2*D*4*D];
__device__ float  g_s2s_whh_t[D*4*D];
__device__ float  g_mem_wih_t[2*D*4*D];
__device__ float  g_lin1_t[5*D*D];
__device__ float  g_hx[NG*D];

__device__ __forceinline__ float sigf(float x) { return 1.0f/(1.0f+expf(-x)); }

__device__ __forceinline__ uint32_t smem_to_u32(const void* p) {
    uint32_t a;
    asm("{ .reg .u64 t; cvta.to.shared.u64 t, %1; cvt.u32.u64 %0, t; }" : "=r"(a) : "l"(p));
    return a;
}

// ---------------- merged prologue ----------------
__global__ void k_prep_all(const float* __restrict__ gru_wih, const float* __restrict__ gru_whh,
                           const float* __restrict__ s2s_wih, const float* __restrict__ s2s_whh,
                           const float* __restrict__ mem_wih, const float* __restrict__ lin1_w,
                           const float* __restrict__ e2_w,
                           const float* __restrict__ x, const float* __restrict__ lin0_w,
                           const float* __restrict__ lin0_b,
                           const float* __restrict__ ea, const float* __restrict__ e1_w,
                           const float* __restrict__ e1_b)
{
    int i = blockIdx.x*blockDim.x + threadIdx.x;
    if (i < 4096*64) {
        int n = i >> 6, k = i & 63;
        float v = e2_w[i];
        __nv_bfloat16 hi = __float2bfloat16(v);
        __nv_bfloat16 lo = __float2bfloat16(v - __bfloat162float(hi));
        g_w2b[n*BK + k]       = hi;
        g_w2b[n*BK + 64 + k]  = hi;
        g_w2b[n*BK + 128 + k] = lo;
    }
    if (i < 192*64) {
        int j = i >> 6, k = i & 63;
        float wv = gru_wih[i];
        __nv_bfloat16 hi = __float2bfloat16(wv);
        __nv_bfloat16 lo = __float2bfloat16(wv - __bfloat162float(hi));
        g_wihb[j*BK + k]       = hi;
        g_wihb[j*BK + 64 + k]  = hi;
        g_wihb[j*BK + 128 + k] = lo;
        float wh = gru_whh[i];
        __nv_bfloat16 hh = __float2bfloat16(wh);
        __nv_bfloat16 hl = __float2bfloat16(wh - __bfloat162float(hh));
        g_whhb[j*BK + k]       = hh;
        g_whhb[j*BK + 64 + k]  = hh;
        g_whhb[j*BK + 128 + k] = hl;
    }
    if (i < 128*256) { int k = i/256,  j = i%256;  g_s2s_wih_t[i] = s2s_wih[j*128+k];
                                                   g_mem_wih_t[i] = mem_wih[j*128+k]; }
    if (i < 64*256)  { int k = i/256,  j = i%256;  g_s2s_whh_t[i] = s2s_whh[j*64+k]; }
    if (i < 320*64)  { int q = i/64,   j = i%64;   g_lin1_t[i] = lin1_w[j*320+q]; }
    if (i < N_NODES) g_cnt[i] = 0;
    if (i < N_NODES*D) {
        int n = i >> 6, j = i & 63;
        float acc = lin0_b[j];
        #pragma unroll
        for (int k = 0; k < 3; k++) acc += x[n*3+k]*lin0_w[j*3+k];
        float v = fmaxf(acc, 0.f);
        g_out[i] = v;
        __nv_bfloat16 hi = __float2bfloat16(v);
        __nv_bfloat16 lo = __float2bfloat16(v - __bfloat162float(hi));
        size_t base = (size_t)n*BK;
        g_outb[base + j]       = hi;
        g_outb[base + 64 + j]  = lo;
        g_outb[base + 128 + j] = hi;
    }
    if (i < N_EDGES*D) {
        int e = i >> 6, j = i & 63;
        float acc = e1_b[j];
        #pragma unroll
        for (int k = 0; k < 6; k++) acc += ea[e*6+k]*e1_w[j*6+k];
        float v = fmaxf(acc, 0.f);
        __nv_bfloat16 hi = __float2bfloat16(v);
        __nv_bfloat16 lo = __float2bfloat16(v - __bfloat162float(hi));
        size_t base = (size_t)e*BK;
        g_heb[base + j]       = hi;
        g_heb[base + 64 + j]  = lo;
        g_heb[base + 128 + j] = hi;
    }
}

// ---------------- HMMA primitives ----------------
__device__ __forceinline__ void mma16816(float c[4], uint32_t a0, uint32_t a1, uint32_t a2, uint32_t a3,
                                         uint32_t b0, uint32_t b1)
{
    asm volatile(
        "mma.sync.aligned.m16n8k16.row.col.f32.bf16.bf16.f32 "
        "{%0,%1,%2,%3}, {%4,%5,%6,%7}, {%8,%9}, {%0,%1,%2,%3};"
        : "+f"(c[0]), "+f"(c[1]), "+f"(c[2]), "+f"(c[3])
        : "r"(a0), "r"(a1), "r"(a2), "r"(a3), "r"(b0), "r"(b1));
}

#define ROWB 400   // bytes per smem row: 4-bank shift/row -> LDSM conflict-free
#define CPITCH 136 // C-stage pitch in halfs

// ---------------- build of g_ew (HMMA plateau ~121 T-MAC/s) ----------------
__global__ void __launch_bounds__(128)
k_build_ew(const float* __restrict__ e2_b)
{
    extern __shared__ char smem[];
    char* sA = smem;
    char* sB = smem + 128*ROWB;
    uint32_t sab = smem_to_u32(smem);
    int tid = threadIdx.x;
    int wid = tid >> 5, lane = tid & 31;
    int e0 = blockIdx.x * 128;
    int n0 = blockIdx.y * 128;

    for (int idx = tid; idx < 128*24; idx += 128) {
        int row = idx / 24, c = idx % 24;
        *(uint4*)(sA + row*ROWB + c*16) = ((const uint4*)(g_heb + (size_t)(e0+row)*BK))[c];
        *(uint4*)(sB + row*ROWB + c*16) = ((const uint4*)(g_w2b + (size_t)(n0+row)*BK))[c];
    }
    __syncthreads();

    int wm = (wid & 1) * 64;
    int wn = (wid >> 1) * 64;
    int grp = lane >> 3;
    int l7  = lane & 7;
    uint32_t aoff = sab + (uint32_t)((wm + (grp & 1)*8 + l7)*ROWB + ((grp >> 1)*8)*2);
    uint32_t boff = sab + (uint32_t)(128*ROWB + (wn + (grp >> 1)*8 + l7)*ROWB + ((grp & 1)*8)*2);

    float acc[4][8][4] = {};
    #pragma unroll
    for (int ks = 0; ks < 12; ks++) {
        uint32_t kb2 = ks * 32;
        uint32_t af[4][4];
        #pragma unroll
        for (int mt = 0; mt < 4; mt++) {
            asm volatile("ldmatrix.sync.aligned.m8n8.x4.shared.b16 {%0,%1,%2,%3}, [%4];"
                : "=r"(af[mt][0]), "=r"(af[mt][1]), "=r"(af[mt][2]), "=r"(af[mt][3])
                : "r"(aoff + mt*16*ROWB + kb2));
        }
        uint32_t bf[8][2];
        #pragma unroll
        for (int np = 0; np < 4; np++) {
            uint32_t r0, r1, r2, r3;
            asm volatile("ldmatrix.sync.aligned.m8n8.x4.shared.b16 {%0,%1,%2,%3}, [%4];"
                : "=r"(r0), "=r"(r1), "=r"(r2), "=r"(r3)
                : "r"(boff + np*16*ROWB + kb2));
            bf[np*2][0] = r0; bf[np*2][1] = r1;
            bf[np*2+1][0] = r2; bf[np*2+1][1] = r3;
        }
        #pragma unroll
        for (int mt = 0; mt < 4; mt++)
            #pragma unroll
            for (int nt = 0; nt < 8; nt++)
                mma16816(acc[mt][nt], af[mt][0], af[mt][1], af[mt][2], af[mt][3],
                         bf[nt][0], bf[nt][1]);
    }

    __syncthreads();
    __half* sC = (__half*)smem;
    int gr = lane >> 2;
    int cc = (lane & 3) * 2;
    #pragma unroll
    for (int nt = 0; nt < 8; nt++) {
        int col = wn + nt*8 + cc;
        float b0v = e2_b[n0 + col], b1v = e2_b[n0 + col + 1];
        #pragma unroll
        for (int mt = 0; mt < 4; mt++) {
            int r0 = wm + mt*16 + gr;
            *(__half2*)(sC + r0*CPITCH + col) =
                __floats2half2_rn(acc[mt][nt][0] + b0v, acc[mt][nt][1] + b1v);
            *(__half2*)(sC + (r0+8)*CPITCH + col) =
                __floats2half2_rn(acc[mt][nt][2] + b0v, acc[mt][nt][3] + b1v);
        }
    }
    __syncthreads();
    for (int idx = tid; idx < 128*16; idx += 128) {
        int row = idx >> 4, ch = idx & 15;
        uint4 v = *(const uint4*)(sC + row*CPITCH + ch*8);
        __stcs((uint4*)(g_ew + (size_t)(e0+row)*4096 + n0 + ch*8), v);
    }
}

// ---------------- HMMA gi/gh: grid (128, 3, 2) ----------
__global__ void __launch_bounds__(128)
k_gih_h(const float* __restrict__ bih, const float* __restrict__ bhh)
{
    extern __shared__ char smem[];
    char* sA = smem;
    char* sB = smem + 128*ROWB;
    uint32_t sab = smem_to_u32(smem);
    int tid = threadIdx.x;
    int wid = tid >> 5, lane = tid & 31;
    int e0 = blockIdx.x * 128;
    int j0 = blockIdx.y * 64;
    int half = blockIdx.z;
    const __nv_bfloat16* A = half ? g_outb : g_mb;
    const __nv_bfloat16* B = half ? g_whhb : g_wihb;
    const float* bias = half ? bhh : bih;
    float* C = half ? g_gh : g_gi;

    for (int idx = tid; idx < 128*24; idx += 128) {
        int row = idx / 24, c = idx % 24;
        *(uint4*)(sA + row*ROWB + c*16) = ((const uint4*)(A + (size_t)(e0+row)*BK))[c];
    }
    for (int idx = tid; idx < 64*24; idx += 128) {
        int row = idx / 24, c = idx % 24;
        *(uint4*)(sB + row*ROWB + c*16) = ((const uint4*)(B + (size_t)(j0+row)*BK))[c];
    }
    __syncthreads();

    int wm = (wid & 1) * 64;
    int wn = (wid >> 1) * 32;
    int grp = lane >> 3;
    int l7  = lane & 7;
    uint32_t aoff = sab + (uint32_t)((wm + (grp & 1)*8 + l7)*ROWB + ((grp >> 1)*8)*2);
    uint32_t boff = sab + (uint32_t)(128*ROWB + (wn + (grp >> 1)*8 + l7)*ROWB + ((grp & 1)*8)*2);

    float acc[4][4][4] = {};
    #pragma unroll
    for (int ks = 0; ks < 12; ks++) {
        uint32_t kb2 = ks * 32;
        uint32_t af[4][4];
        #pragma unroll
        for (int mt = 0; mt < 4; mt++) {
            asm volatile("ldmatrix.sync.aligned.m8n8.x4.shared.b16 {%0,%1,%2,%3}, [%4];"
                : "=r"(af[mt][0]), "=r"(af[mt][1]), "=r"(af[mt][2]), "=r"(af[mt][3])
                : "r"(aoff + mt*16*ROWB + kb2));
        }
        uint32_t bf[4][2];
        #pragma unroll
        for (int np = 0; np < 2; np++) {
            uint32_t r0, r1, r2, r3;
            asm volatile("ldmatrix.sync.aligned.m8n8.x4.shared.b16 {%0,%1,%2,%3}, [%4];"
                : "=r"(r0), "=r"(r1), "=r"(r2), "=r"(r3)
                : "r"(boff + np*16*ROWB + kb2));
            bf[np*2][0] = r0; bf[np*2][1] = r1;
            bf[np*2+1][0] = r2; bf[np*2+1][1] = r3;
        }
        #pragma unroll
        for (int mt = 0; mt < 4; mt++)
            #pragma unroll
            for (int nt = 0; nt < 4; nt++)
                mma16816(acc[mt][nt], af[mt][0], af[mt][1], af[mt][2], af[mt][3],
                         bf[nt][0], bf[nt][1]);
    }

    int gr = lane >> 2;
    int cc = (lane & 3) * 2;
    #pragma unroll
    for (int nt = 0; nt < 4; nt++) {
        int col = j0 + wn + nt*8 + cc;
        float b0v = bias[col], b1v = bias[col+1];
        #pragma unroll
        for (int mt = 0; mt < 4; mt++) {
            int r0 = e0 + wm + mt*16 + gr;
            *(float2*)(C + (size_t)r0*192 + col) =
                make_float2(acc[mt][nt][0] + b0v, acc[mt][nt][1] + b1v);
            *(float2*)(C + (size_t)(r0+8)*192 + col) =
                make_float2(acc[mt][nt][2] + b0v, acc[mt][nt][3] + b1v);
        }
    }
}

// ---------------- CSR build (R13 layout: scan + multi-block fill) ----------------
__global__ void k_count(const int* __restrict__ dst)
{
    int e = blockIdx.x*blockDim.x + threadIdx.x;
    if (e < N_EDGES) atomicAdd(&g_cnt[dst[e]], 1);
}

__global__ void __launch_bounds__(1024) k_scan()
{
    __shared__ int part[1024];
    int tid = threadIdx.x;
    int base = tid*16;
    int loc[16]; int tsum = 0;
    #pragma unroll
    for (int t = 0; t < 16; t++) { loc[t] = g_cnt[base+t]; tsum += loc[t]; }
    part[tid] = tsum;
    __syncthreads();
    for (int d = 1; d < 1024; d <<= 1) {
        int v = 0;
        if (tid >= d) v = part[tid-d];
        __syncthreads();
        if (tid >= d) part[tid] += v;
        __syncthreads();
    }
    int run = part[tid] - tsum;
    #pragma unroll
    for (int t = 0; t < 16; t++) { g_eoff[base+t] = run; run += loc[t]; }
    if (tid == 1023) g_eoff[N_NODES] = part[1023];
    for (int i = tid; i < N_NODES; i += 1024) g_cur[i] = 0;
}

__global__ void k_fill(const int* __restrict__ dst)
{
    int e = blockIdx.x*blockDim.x + threadIdx.x;
    if (e < N_EDGES) {
        int d = dst[e];
        int p = atomicAdd(&g_cur[d], 1);
        g_eid[g_eoff[d] + p] = e;
    }
}

// ---------------- msg: sequential ew stream, streaming-cache hints ----------------
__global__ void __launch_bounds__(256)
k_msg_w(const int* __restrict__ src)
{
    __shared__ float s_o[8][64];
    int w = threadIdx.x >> 5;
    int lane = threadIdx.x & 31;
    int e = blockIdx.x*8 + w;
    int s = src[e];
    s_o[w][lane]      = g_out[s*64 + lane];
    s_o[w][lane + 32] = g_out[s*64 + 32 + lane];
    __syncwarp();
    int rgrp = lane >> 3;
    float acc[8] = {};
    const uint4* ew4 = (const uint4*)(g_ew + (size_t)e*4096);
    #pragma unroll
    for (int i = 0; i < 16; i++) {
        int row = i*4 + rgrp;
        uint4 v = __ldcs(ew4 + i*32 + lane);        // evict-first: 256MB stream, never reused in L2
        float a = s_o[w][row];
        const __half2* hp = (const __half2*)&v;
        #pragma unroll
        for (int q = 0; q < 4; q++) {
            float2 f = __half22float2(hp[q]);
            acc[2*q]   += a*f.x;
            acc[2*q+1] += a*f.y;
        }
    }
    #pragma unroll
    for (int q = 0; q < 8; q++) {
        acc[q] += __shfl_xor_sync(0xffffffffu, acc[q], 8);
        acc[q] += __shfl_xor_sync(0xffffffffu, acc[q], 16);
    }
    if (lane < 8) {
        float4* op = (float4*)(g_msg + (size_t)e*64 + lane*8);
        __stcs(op,     make_float4(acc[0], acc[1], acc[2], acc[3]));
        __stcs(op + 1, make_float4(acc[4], acc[5], acc[6], acc[7]));
    }
}

// ---------------- node GEMM + CSR-mean (g_eid gather); writes split-bf16 g_mb ----------------
__global__ void __launch_bounds__(256)
k_gemm1(const float* __restrict__ Bext, const float* __restrict__ bias)
{
    __shared__ __align__(16) float sAt[64][68];
    __shared__ __align__(16) float sB[64][64];
    int tid = threadIdx.x;
    int e0 = blockIdx.x * 64;
    for (int l = tid; l < 64*64; l += 256) {
        int r = l >> 6, c = l & 63;
        sAt[c][r] = g_out[(e0 + r)*64 + c];
        sB[r][c]  = Bext[r*64 + c];
    }
    __syncthreads();
    int te = (tid >> 4) << 2;
    int tj = (tid & 15) << 2;
    float acc[4][4] = {};
    #pragma unroll
    for (int k = 0; k < 64; k++) {
        float4 a = *(const float4*)&sAt[k][te];
        float4 b = *(const float4*)&sB[k][tj];
        acc[0][0] += a.x*b.x; acc[0][1] += a.x*b.y; acc[0][2] += a.x*b.z; acc[0][3] += a.x*b.w;
        acc[1][0] += a.y*b.x; acc[1][1] += a.y*b.y; acc[1][2] += a.y*b.z; acc[1][3] += a.y*b.w;
        acc[2][0] += a.z*b.x; acc[2][1] += a.z*b.y; acc[2][2] += a.z*b.z; acc[2][3] += a.z*b.w;
        acc[3][0] += a.w*b.x; acc[3][1] += a.w*b.y; acc[3][2] += a.w*b.z; acc[3][3] += a.w*b.w;
    }
    #pragma unroll
    for (int ii = 0; ii < 4; ii++) {
        int row = e0 + te + ii;
        int b0 = g_eoff[row], b1 = g_eoff[row+1];
        float s0 = 0.f, s1 = 0.f, s2 = 0.f, s3 = 0.f;
        for (int p = b0; p < b1; p++) {
            int e = g_eid[p];
            float4 v = __ldcs((const float4*)(g_msg + (size_t)e*64 + tj));
            s0 += v.x; s1 += v.y; s2 += v.z; s3 += v.w;
        }
        float inv = 1.0f/fmaxf((float)(b1 - b0), 1.f);
        float vals[4] = { fmaxf(acc[ii][0] + s0*inv + bias[tj+0], 0.f),
                          fmaxf(acc[ii][1] + s1*inv + bias[tj+1], 0.f),
                          fmaxf(acc[ii][2] + s2*inv + bias[tj+2], 0.f),
                          fmaxf(acc[ii][3] + s3*inv + bias[tj+3], 0.f) };
        size_t base = (size_t)row*BK;
        #pragma unroll
        for (int jj = 0; jj < 4; jj++) {
            float v = vals[jj];
            __nv_bfloat16 hi = __float2bfloat16(v);
            __nv_bfloat16 lo = __float2bfloat16(v - __bfloat162float(hi));
            g_mb[base + tj + jj]        = hi;
            g_mb[base + 64 + tj + jj]   = lo;
            g_mb[base + 128 + tj + jj]  = hi;
        }
    }
}

__global__ void k_gru()
{
    int i = blockIdx.x*blockDim.x + threadIdx.x;
    int n = i >> 6, j = i & 63;
    const float* gi = g_gi + n*192;
    const float* gh = g_gh + n*192;
    float r  = sigf(gi[j]      + gh[j]);
    float z  = sigf(gi[64+j]   + gh[64+j]);
    float nn = tanhf(gi[128+j] + r*gh[128+j]);
    float h  = g_out[i];
    float hn = (1.f - z)*nn + z*h;
    g_out[i] = hn;
    __nv_bfloat16 hi = __float2bfloat16(hn);
    __nv_bfloat16 lo = __float2bfloat16(hn - __bfloat162float(hi));
    size_t base = (size_t)n*BK;
    g_outb[base + j]       = hi;
    g_outb[base + 64 + j]  = lo;
    g_outb[base + 128 + j] = hi;
}

// Set2Set (6 steps) + memory LSTM; one block per graph
__global__ void __launch_bounds__(256)
k_s2s(const float* __restrict__ s2s_bih, const float* __restrict__ s2s_bhh,
      const float* __restrict__ mem_bih, const float* __restrict__ mem_bhh,
      float* __restrict__ d_out, int out_size)
{
    __shared__ float so[64*65];
    __shared__ float sq[128];
    __shared__ float shs[64], scs[64], sg[256], se[64];
    __shared__ float sred[2];
    int g = blockIdx.x, tid = threadIdx.x;
    for (int l = tid; l < 64*64; l += 256) {
        int n = l >> 6, c = l & 63;
        so[n*65+c] = g_out[(g*64+n)*64 + c];
    }
    if (tid < 128) sq[tid] = 0.f;
    if (tid < 64) { shs[tid] = 0.f; scs[tid] = 0.f; }
    __syncthreads();
    for (int step = 0; step < 6; step++) {
        float acc = s2s_bih[tid] + s2s_bhh[tid];
        #pragma unroll 4
        for (int k = 0; k < 128; k++) acc += sq[k]*g_s2s_wih_t[k*256+tid];
        #pragma unroll 4
        for (int k = 0; k < 64;  k++) acc += shs[k]*g_s2s_whh_t[k*256+tid];
        sg[tid] = acc;
        __syncthreads();
        if (tid < 64) {
            float iv = sg[tid], fv = sg[64+tid], gv = sg[128+tid], ov = sg[192+tid];
            float c = sigf(fv)*scs[tid] + sigf(iv)*tanhf(gv);
            scs[tid] = c;
            shs[tid] = sigf(ov)*tanhf(c);
        }
        __syncthreads();
        if (tid < 64) {
            float a = 0.f;
            #pragma unroll 8
            for (int k = 0; k < 64; k++) a += so[tid*65+k]*shs[k];
            se[tid] = a;
        }
        __syncthreads();
        if (tid < 32) {
            float m1 = fmaxf(se[tid], se[tid+32]);
            #pragma unroll
            for (int off = 16; off; off >>= 1) m1 = fmaxf(m1, __shfl_xor_sync(0xffffffffu, m1, off));
            if (tid == 0) sred[0] = m1;
        }
        __syncthreads();
        if (tid < 64) se[tid] = expf(se[tid] - sred[0]);
        __syncthreads();
        if (tid < 32) {
            float s1 = se[tid] + se[tid+32];
            #pragma unroll
            for (int off = 16; off; off >>= 1) s1 += __shfl_xor_sync(0xffffffffu, s1, off);
            if (tid == 0) sred[1] = s1;
        }
        __syncthreads();
        if (tid < 64) {
            float inv = 1.f/sred[1];
            float racc = 0.f;
            #pragma unroll 8
            for (int n = 0; n < 64; n++) racc += se[n]*so[n*65+tid];
            sq[64+tid] = racc*inv;
            sq[tid] = shs[tid];
        }
        __syncthreads();
    }
    float acc = mem_bih[tid] + mem_bhh[tid];
    #pragma unroll 4
    for (int k = 0; k < 128; k++) acc += sq[k]*g_mem_wih_t[k*256+tid];
    sg[tid] = acc;
    __syncthreads();
    if (tid < 64) {
        float iv = sg[tid], gv = sg[128+tid], ov = sg[192+tid];
        float cx = sigf(iv)*tanhf(gv);
        float hx = sigf(ov)*tanhf(cx);
        g_hx[g*64+tid] = hx;
        if (out_size >= NT*6 + 2*NG*D) {
            d_out[NT*6 + g*64 + tid]        = hx;
            d_out[NT*6 + NG*D + g*64 + tid] = cx;
        }
    }
}

// head
__global__ void __launch_bounds__(64)
k_final(const int* __restrict__ nonring, const int* __restrict__ nrbidx,
        const float* __restrict__ lin1_b, const float* __restrict__ lin2_w,
        const float* __restrict__ lin2_b, float* __restrict__ d_out)
{
    __shared__ float sf[320];
    __shared__ float so1[64];
    int r = blockIdx.x, tid = threadIdx.x;
    int ch = r / 48;
    int t  = (r % 48) * 64 + tid;
    sf[tid*5 + 0] = g_hx[nrbidx[t]*64 + ch];
    #pragma unroll
    for (int s = 1; s < 5; s++) {
        int node = nonring[(s-1)*NT + t];
        sf[tid*5 + s] = g_out[node*64 + ch];
    }
    __syncthreads();
    float acc = lin1_b[tid];
    #pragma unroll 8
    for (int q = 0; q < 320; q++) acc += sf[q]*g_lin1_t[q*64+tid];
    so1[tid] = fmaxf(acc, 0.f);
    __syncthreads();
    if (tid < 6) {
        float a2 = lin2_b[tid];
        #pragma unroll 8
        for (int k = 0; k < 64; k++) a2 += so1[k]*lin2_w[tid*64+k];
        d_out[r*6 + tid] = a2;
    }
}

extern "C" void kernel_launch(void* const* d_in, const int* in_sizes, int n_in,
                              void* d_out, int out_size)
{
    const float* x        = (const float*)d_in[0];
    const float* ea       = (const float*)d_in[1];
    const int*   eidx     = (const int*)  d_in[2];
    const int*   nonring  = (const int*)  d_in[4];
    const int*   nrbidx   = (const int*)  d_in[5];
    int base = (n_in >= 32) ? 8 : 6;
    const float* lin0_w  = (const float*)d_in[base+0];
    const float* lin0_b  = (const float*)d_in[base+1];
    const float* e1_w    = (const float*)d_in[base+2];
    const float* e1_b    = (const float*)d_in[base+3];
    const float* e2_w    = (const float*)d_in[base+4];
    const float* e2_b    = (const float*)d_in[base+5];
    const float* root_w  = (const float*)d_in[base+6];
    const float* conv_b  = (const float*)d_in[base+7];
    const float* gru_wih = (const float*)d_in[base+8];
    const float* gru_whh = (const float*)d_in[base+9];
    const float* gru_bih = (const float*)d_in[base+10];
    const float* gru_bhh = (const float*)d_in[base+11];
    const float* s2s_wih = (const float*)d_in[base+12];
    const float* s2s_whh = (const float*)d_in[base+13];
    const float* s2s_bih = (const float*)d_in[base+14];
    const float* s2s_bhh = (const float*)d_in[base+15];
    const float* mem_wih = (const float*)d_in[base+16];
    const float* mem_bih = (const float*)d_in[base+18];
    const float* mem_bhh = (const float*)d_in[base+19];
    const float* lin1_w  = (const float*)d_in[base+20];
    const float* lin1_b  = (const float*)d_in[base+21];
    const float* lin2_w  = (const float*)d_in[base+22];
    const float* lin2_b  = (const float*)d_in[base+23];
    float* out = (float*)d_out;

    const int* src = eidx;
    const int* dst = eidx + N_EDGES;

    const int BUILD_SMEM = 256 * ROWB;       // 102400 bytes
    const int GIH_SMEM   = 192 * ROWB;       // 76800 bytes
    static int smem_set = 0;
    if (!smem_set) {
        cudaFuncSetAttribute(k_build_ew, cudaFuncAttributeMaxDynamicSharedMemorySize, BUILD_SMEM);
        cudaFuncSetAttribute(k_gih_h,    cudaFuncAttributeMaxDynamicSharedMemorySize, GIH_SMEM);
        smem_set = 1;
    }

    k_prep_all<<<(N_EDGES*D)/256, 256>>>(gru_wih, gru_whh, s2s_wih, s2s_whh, mem_wih,
                                         lin1_w, e2_w, x, lin0_w, lin0_b, ea, e1_w, e1_b);
    k_count<<<N_EDGES/256, 256>>>(dst);
    k_scan<<<1, 1024>>>();
    k_build_ew<<<dim3(N_EDGES/128, 4096/128), 128, BUILD_SMEM>>>(e2_b);   // launch #4 (profiled)
    k_fill<<<N_EDGES/256, 256>>>(dst);

    for (int it = 0; it < 6; it++) {
        k_msg_w<<<N_EDGES/8, 256>>>(src);
        k_gemm1<<<N_NODES/64, 256>>>(root_w, conv_b);
        k_gih_h<<<dim3(N_NODES/128, 3, 2), 128, GIH_SMEM>>>(gru_bih, gru_bhh);
        k_gru<<<(N_NODES*D)/256, 256>>>();
    }

    k_s2s<<<NG, 256>>>(s2s_bih, s2s_bhh, mem_bih, mem_bhh, out, out_size);
    k_final<<<NT, 64>>>(nonring, nrbidx, lin1_b, lin2_w, lin2_b, out);
}

// round 17
// speedup vs baseline: 1.4609x; 1.0101x over previous
#include <cuda_runtime.h>
#include <cuda_fp16.h>
#include <cuda_bf16.h>
#include <math.h>
#include <stdint.h>

#define N_NODES 16384
#define N_EDGES 32768
#define NG 256
#define TPG 12
#define NT (NG*TPG)
#define D 64
#define BK 192          // split-bf16 K extent (3 x 64)

__device__ float  g_out[N_NODES*D];
__device__ __nv_bfloat16 g_outb[(size_t)N_NODES*BK];   // split-bf16 of out/h  [hi|lo|hi]
__device__ __nv_bfloat16 g_mb  [(size_t)N_NODES*BK];   // split-bf16 of m      [hi|lo|hi]
__device__ __nv_bfloat16 g_heb[(size_t)N_EDGES*BK];
__device__ __nv_bfloat16 g_w2b[4096*BK];
__device__ __nv_bfloat16 g_wihb[192*BK];               // split-B [hi|hi|lo]
__device__ __nv_bfloat16 g_whhb[192*BK];
__device__ __half g_ew [(size_t)N_EDGES*D*D];
__device__ float  g_msg[(size_t)N_EDGES*D];            // indexed by edge id (sequential ew stream)
__device__ float  g_gi [N_NODES*3*D];
__device__ float  g_gh [N_NODES*3*D];
__device__ int    g_cnt[N_NODES];
__device__ int    g_cur[N_NODES];
__device__ int    g_eoff[N_NODES+1];
__device__ int    g_eid[N_EDGES];
__device__ float  g_s2s_wih_t[2*D*4*D];
__device__ float  g_s2s_whh_t[D*4*D];
__device__ float  g_mem_wih_t[2*D*4*D];
__device__ float  g_lin1_t[5*D*D];
__device__ float  g_hx[NG*D];

__device__ __forceinline__ float sigf(float x) { return 1.0f/(1.0f+expf(-x)); }

__device__ __forceinline__ uint32_t smem_to_u32(const void* p) {
    uint32_t a;
    asm("{ .reg .u64 t; cvta.to.shared.u64 t, %1; cvt.u32.u64 %0, t; }" : "=r"(a) : "l"(p));
    return a;
}

// ---------------- merged prologue ----------------
__global__ void k_prep_all(const float* __restrict__ gru_wih, const float* __restrict__ gru_whh,
                           const float* __restrict__ s2s_wih, const float* __restrict__ s2s_whh,
                           const float* __restrict__ mem_wih, const float* __restrict__ lin1_w,
                           const float* __restrict__ e2_w,
                           const float* __restrict__ x, const float* __restrict__ lin0_w,
                           const float* __restrict__ lin0_b,
                           const float* __restrict__ ea, const float* __restrict__ e1_w,
                           const float* __restrict__ e1_b)
{
    int i = blockIdx.x*blockDim.x + threadIdx.x;
    if (i < 4096*64) {
        int n = i >> 6, k = i & 63;
        float v = e2_w[i];
        __nv_bfloat16 hi = __float2bfloat16(v);
        __nv_bfloat16 lo = __float2bfloat16(v - __bfloat162float(hi));
        g_w2b[n*BK + k]       = hi;
        g_w2b[n*BK + 64 + k]  = hi;
        g_w2b[n*BK + 128 + k] = lo;
    }
    if (i < 192*64) {
        int j = i >> 6, k = i & 63;
        float wv = gru_wih[i];
        __nv_bfloat16 hi = __float2bfloat16(wv);
        __nv_bfloat16 lo = __float2bfloat16(wv - __bfloat162float(hi));
        g_wihb[j*BK + k]       = hi;
        g_wihb[j*BK + 64 + k]  = hi;
        g_wihb[j*BK + 128 + k] = lo;
        float wh = gru_whh[i];
        __nv_bfloat16 hh = __float2bfloat16(wh);
        __nv_bfloat16 hl = __float2bfloat16(wh - __bfloat162float(hh));
        g_whhb[j*BK + k]       = hh;
        g_whhb[j*BK + 64 + k]  = hh;
        g_whhb[j*BK + 128 + k] = hl;
    }
    if (i < 128*256) { int k = i/256,  j = i%256;  g_s2s_wih_t[i] = s2s_wih[j*128+k];
                                                   g_mem_wih_t[i] = mem_wih[j*128+k]; }
    if (i < 64*256)  { int k = i/256,  j = i%256;  g_s2s_whh_t[i] = s2s_whh[j*64+k]; }
    if (i < 320*64)  { int q = i/64,   j = i%64;   g_lin1_t[i] = lin1_w[j*320+q]; }
    if (i < N_NODES) g_cnt[i] = 0;
    if (i < N_NODES*D) {
        int n = i >> 6, j = i & 63;
        float acc = lin0_b[j];
        #pragma unroll
        for (int k = 0; k < 3; k++) acc += x[n*3+k]*lin0_w[j*3+k];
        float v = fmaxf(acc, 0.f);
        g_out[i] = v;
        __nv_bfloat16 hi = __float2bfloat16(v);
        __nv_bfloat16 lo = __float2bfloat16(v - __bfloat162float(hi));
        size_t base = (size_t)n*BK;
        g_outb[base + j]       = hi;
        g_outb[base + 64 + j]  = lo;
        g_outb[base + 128 + j] = hi;
    }
    if (i < N_EDGES*D) {
        int e = i >> 6, j = i & 63;
        float acc = e1_b[j];
        #pragma unroll
        for (int k = 0; k < 6; k++) acc += ea[e*6+k]*e1_w[j*6+k];
        float v = fmaxf(acc, 0.f);
        __nv_bfloat16 hi = __float2bfloat16(v);
        __nv_bfloat16 lo = __float2bfloat16(v - __bfloat162float(hi));
        size_t base = (size_t)e*BK;
        g_heb[base + j]       = hi;
        g_heb[base + 64 + j]  = lo;
        g_heb[base + 128 + j] = hi;
    }
}

// ---------------- HMMA primitives ----------------
__device__ __forceinline__ void mma16816(float c[4], uint32_t a0, uint32_t a1, uint32_t a2, uint32_t a3,
                                         uint32_t b0, uint32_t b1)
{
    asm volatile(
        "mma.sync.aligned.m16n8k16.row.col.f32.bf16.bf16.f32 "
        "{%0,%1,%2,%3}, {%4,%5,%6,%7}, {%8,%9}, {%0,%1,%2,%3};"
        : "+f"(c[0]), "+f"(c[1]), "+f"(c[2]), "+f"(c[3])
        : "r"(a0), "r"(a1), "r"(a2), "r"(a3), "r"(b0), "r"(b1));
}

#define ROWB 400   // bytes per smem row: 4-bank shift/row -> LDSM conflict-free
#define CPITCH 136 // C-stage pitch in halfs

// ---------------- build of g_ew (HMMA plateau ~121 T-MAC/s) ----------------
__global__ void __launch_bounds__(128)
k_build_ew(const float* __restrict__ e2_b)
{
    extern __shared__ char smem[];
    char* sA = smem;
    char* sB = smem + 128*ROWB;
    uint32_t sab = smem_to_u32(smem);
    int tid = threadIdx.x;
    int wid = tid >> 5, lane = tid & 31;
    int e0 = blockIdx.x * 128;
    int n0 = blockIdx.y * 128;

    for (int idx = tid; idx < 128*24; idx += 128) {
        int row = idx / 24, c = idx % 24;
        *(uint4*)(sA + row*ROWB + c*16) = ((const uint4*)(g_heb + (size_t)(e0+row)*BK))[c];
        *(uint4*)(sB + row*ROWB + c*16) = ((const uint4*)(g_w2b + (size_t)(n0+row)*BK))[c];
    }
    __syncthreads();

    int wm = (wid & 1) * 64;
    int wn = (wid >> 1) * 64;
    int grp = lane >> 3;
    int l7  = lane & 7;
    uint32_t aoff = sab + (uint32_t)((wm + (grp & 1)*8 + l7)*ROWB + ((grp >> 1)*8)*2);
    uint32_t boff = sab + (uint32_t)(128*ROWB + (wn + (grp >> 1)*8 + l7)*ROWB + ((grp & 1)*8)*2);

    float acc[4][8][4] = {};
    #pragma unroll
    for (int ks = 0; ks < 12; ks++) {
        uint32_t kb2 = ks * 32;
        uint32_t af[4][4];
        #pragma unroll
        for (int mt = 0; mt < 4; mt++) {
            asm volatile("ldmatrix.sync.aligned.m8n8.x4.shared.b16 {%0,%1,%2,%3}, [%4];"
                : "=r"(af[mt][0]), "=r"(af[mt][1]), "=r"(af[mt][2]), "=r"(af[mt][3])
                : "r"(aoff + mt*16*ROWB + kb2));
        }
        uint32_t bf[8][2];
        #pragma unroll
        for (int np = 0; np < 4; np++) {
            uint32_t r0, r1, r2, r3;
            asm volatile("ldmatrix.sync.aligned.m8n8.x4.shared.b16 {%0,%1,%2,%3}, [%4];"
                : "=r"(r0), "=r"(r1), "=r"(r2), "=r"(r3)
                : "r"(boff + np*16*ROWB + kb2));
            bf[np*2][0] = r0; bf[np*2][1] = r1;
            bf[np*2+1][0] = r2; bf[np*2+1][1] = r3;
        }
        #pragma unroll
        for (int mt = 0; mt < 4; mt++)
            #pragma unroll
            for (int nt = 0; nt < 8; nt++)
                mma16816(acc[mt][nt], af[mt][0], af[mt][1], af[mt][2], af[mt][3],
                         bf[nt][0], bf[nt][1]);
    }

    __syncthreads();
    __half* sC = (__half*)smem;
    int gr = lane >> 2;
    int cc = (lane & 3) * 2;
    #pragma unroll
    for (int nt = 0; nt < 8; nt++) {
        int col = wn + nt*8 + cc;
        float b0v = e2_b[n0 + col], b1v = e2_b[n0 + col + 1];
        #pragma unroll
        for (int mt = 0; mt < 4; mt++) {
            int r0 = wm + mt*16 + gr;
            *(__half2*)(sC + r0*CPITCH + col) =
                __floats2half2_rn(acc[mt][nt][0] + b0v, acc[mt][nt][1] + b1v);
            *(__half2*)(sC + (r0+8)*CPITCH + col) =
                __floats2half2_rn(acc[mt][nt][2] + b0v, acc[mt][nt][3] + b1v);
        }
    }
    __syncthreads();
    for (int idx = tid; idx < 128*16; idx += 128) {
        int row = idx >> 4, ch = idx & 15;
        uint4 v = *(const uint4*)(sC + row*CPITCH + ch*8);
        __stcs((uint4*)(g_ew + (size_t)(e0+row)*4096 + n0 + ch*8), v);
    }
}

// ---------------- HMMA gi/gh: grid (128, 3), half selects gate set ----------
__global__ void __launch_bounds__(128)
k_gih_h(const float* __restrict__ bih, const float* __restrict__ bhh, int half)
{
    extern __shared__ char smem[];
    char* sA = smem;
    char* sB = smem + 128*ROWB;
    uint32_t sab = smem_to_u32(smem);
    int tid = threadIdx.x;
    int wid = tid >> 5, lane = tid & 31;
    int e0 = blockIdx.x * 128;
    int j0 = blockIdx.y * 64;
    const __nv_bfloat16* A = half ? g_outb : g_mb;
    const __nv_bfloat16* B = half ? g_whhb : g_wihb;
    const float* bias = half ? bhh : bih;
    float* C = half ? g_gh : g_gi;

    for (int idx = tid; idx < 128*24; idx += 128) {
        int row = idx / 24, c = idx % 24;
        *(uint4*)(sA + row*ROWB + c*16) = ((const uint4*)(A + (size_t)(e0+row)*BK))[c];
    }
    for (int idx = tid; idx < 64*24; idx += 128) {
        int row = idx / 24, c = idx % 24;
        *(uint4*)(sB + row*ROWB + c*16) = ((const uint4*)(B + (size_t)(j0+row)*BK))[c];
    }
    __syncthreads();

    int wm = (wid & 1) * 64;
    int wn = (wid >> 1) * 32;
    int grp = lane >> 3;
    int l7  = lane & 7;
    uint32_t aoff = sab + (uint32_t)((wm + (grp & 1)*8 + l7)*ROWB + ((grp >> 1)*8)*2);
    uint32_t boff = sab + (uint32_t)(128*ROWB + (wn + (grp >> 1)*8 + l7)*ROWB + ((grp & 1)*8)*2);

    float acc[4][4][4] = {};
    #pragma unroll
    for (int ks = 0; ks < 12; ks++) {
        uint32_t kb2 = ks * 32;
        uint32_t af[4][4];
        #pragma unroll
        for (int mt = 0; mt < 4; mt++) {
            asm volatile("ldmatrix.sync.aligned.m8n8.x4.shared.b16 {%0,%1,%2,%3}, [%4];"
                : "=r"(af[mt][0]), "=r"(af[mt][1]), "=r"(af[mt][2]), "=r"(af[mt][3])
                : "r"(aoff + mt*16*ROWB + kb2));
        }
        uint32_t bf[4][2];
        #pragma unroll
        for (int np = 0; np < 2; np++) {
            uint32_t r0, r1, r2, r3;
            asm volatile("ldmatrix.sync.aligned.m8n8.x4.shared.b16 {%0,%1,%2,%3}, [%4];"
                : "=r"(r0), "=r"(r1), "=r"(r2), "=r"(r3)
                : "r"(boff + np*16*ROWB + kb2));
            bf[np*2][0] = r0; bf[np*2][1] = r1;
            bf[np*2+1][0] = r2; bf[np*2+1][1] = r3;
        }
        #pragma unroll
        for (int mt = 0; mt < 4; mt++)
            #pragma unroll
            for (int nt = 0; nt < 4; nt++)
                mma16816(acc[mt][nt], af[mt][0], af[mt][1], af[mt][2], af[mt][3],
                         bf[nt][0], bf[nt][1]);
    }

    int gr = lane >> 2;
    int cc = (lane & 3) * 2;
    #pragma unroll
    for (int nt = 0; nt < 4; nt++) {
        int col = j0 + wn + nt*8 + cc;
        float b0v = bias[col], b1v = bias[col+1];
        #pragma unroll
        for (int mt = 0; mt < 4; mt++) {
            int r0 = e0 + wm + mt*16 + gr;
            *(float2*)(C + (size_t)r0*192 + col) =
                make_float2(acc[mt][nt][0] + b0v, acc[mt][nt][1] + b1v);
            *(float2*)(C + (size_t)(r0+8)*192 + col) =
                make_float2(acc[mt][nt][2] + b0v, acc[mt][nt][3] + b1v);
        }
    }
}

// ---------------- CSR build ----------------
__global__ void k_count(const int* __restrict__ dst)
{
    int e = blockIdx.x*blockDim.x + threadIdx.x;
    if (e < N_EDGES) atomicAdd(&g_cnt[dst[e]], 1);
}

__global__ void __launch_bounds__(1024) k_scan()
{
    __shared__ int part[1024];
    int tid = threadIdx.x;
    int base = tid*16;
    int loc[16]; int tsum = 0;
    #pragma unroll
    for (int t = 0; t < 16; t++) { loc[t] = g_cnt[base+t]; tsum += loc[t]; }
    part[tid] = tsum;
    __syncthreads();
    for (int d = 1; d < 1024; d <<= 1) {
        int v = 0;
        if (tid >= d) v = part[tid-d];
        __syncthreads();
        if (tid >= d) part[tid] += v;
        __syncthreads();
    }
    int run = part[tid] - tsum;
    #pragma unroll
    for (int t = 0; t < 16; t++) { g_eoff[base+t] = run; run += loc[t]; }
    if (tid == 1023) g_eoff[N_NODES] = part[1023];
    for (int i = tid; i < N_NODES; i += 1024) g_cur[i] = 0;
}

__global__ void k_fill(const int* __restrict__ dst)
{
    int e = blockIdx.x*blockDim.x + threadIdx.x;
    if (e < N_EDGES) {
        int d = dst[e];
        int p = atomicAdd(&g_cur[d], 1);
        g_eid[g_eoff[d] + p] = e;
    }
}

// ---------------- msg: sequential ew stream, streaming-cache hints ----------------
__global__ void __launch_bounds__(256)
k_msg_w(const int* __restrict__ src)
{
    __shared__ float s_o[8][64];
    int w = threadIdx.x >> 5;
    int lane = threadIdx.x & 31;
    int e = blockIdx.x*8 + w;
    int s = src[e];
    s_o[w][lane]      = g_out[s*64 + lane];
    s_o[w][lane + 32] = g_out[s*64 + 32 + lane];
    __syncwarp();
    int rgrp = lane >> 3;
    float acc[8] = {};
    const uint4* ew4 = (const uint4*)(g_ew + (size_t)e*4096);
    #pragma unroll
    for (int i = 0; i < 16; i++) {
        int row = i*4 + rgrp;
        uint4 v = __ldcs(ew4 + i*32 + lane);        // evict-first: 256MB stream
        float a = s_o[w][row];
        const __half2* hp = (const __half2*)&v;
        #pragma unroll
        for (int q = 0; q < 4; q++) {
            float2 f = __half22float2(hp[q]);
            acc[2*q]   += a*f.x;
            acc[2*q+1] += a*f.y;
        }
    }
    #pragma unroll
    for (int q = 0; q < 8; q++) {
        acc[q] += __shfl_xor_sync(0xffffffffu, acc[q], 8);
        acc[q] += __shfl_xor_sync(0xffffffffu, acc[q], 16);
    }
    if (lane < 8) {
        float4* op = (float4*)(g_msg + (size_t)e*64 + lane*8);
        __stcs(op,     make_float4(acc[0], acc[1], acc[2], acc[3]));
        __stcs(op + 1, make_float4(acc[4], acc[5], acc[6], acc[7]));
    }
}

// ---------------- node GEMM + CSR-mean (g_eid gather); writes split-bf16 g_mb ----------------
__global__ void __launch_bounds__(256)
k_gemm1(const float* __restrict__ Bext, const float* __restrict__ bias)
{
    __shared__ __align__(16) float sAt[64][68];
    __shared__ __align__(16) float sB[64][64];
    int tid = threadIdx.x;
    int e0 = blockIdx.x * 64;
    for (int l = tid; l < 64*64; l += 256) {
        int r = l >> 6, c = l & 63;
        sAt[c][r] = g_out[(e0 + r)*64 + c];
        sB[r][c]  = Bext[r*64 + c];
    }
    __syncthreads();
    int te = (tid >> 4) << 2;
    int tj = (tid & 15) << 2;
    float acc[4][4] = {};
    #pragma unroll
    for (int k = 0; k < 64; k++) {
        float4 a = *(const float4*)&sAt[k][te];
        float4 b = *(const float4*)&sB[k][tj];
        acc[0][0] += a.x*b.x; acc[0][1] += a.x*b.y; acc[0][2] += a.x*b.z; acc[0][3] += a.x*b.w;
        acc[1][0] += a.y*b.x; acc[1][1] += a.y*b.y; acc[1][2] += a.y*b.z; acc[1][3] += a.y*b.w;
        acc[2][0] += a.z*b.x; acc[2][1] += a.z*b.y; acc[2][2] += a.z*b.z; acc[2][3] += a.z*b.w;
        acc[3][0] += a.w*b.x; acc[3][1] += a.w*b.y; acc[3][2] += a.w*b.z; acc[3][3] += a.w*b.w;
    }
    #pragma unroll
    for (int ii = 0; ii < 4; ii++) {
        int row = e0 + te + ii;
        int b0 = g_eoff[row], b1 = g_eoff[row+1];
        float s0 = 0.f, s1 = 0.f, s2 = 0.f, s3 = 0.f;
        for (int p = b0; p < b1; p++) {
            int e = g_eid[p];
            float4 v = __ldcs((const float4*)(g_msg + (size_t)e*64 + tj));
            s0 += v.x; s1 += v.y; s2 += v.z; s3 += v.w;
        }
        float inv = 1.0f/fmaxf((float)(b1 - b0), 1.f);
        float vals[4] = { fmaxf(acc[ii][0] + s0*inv + bias[tj+0], 0.f),
                          fmaxf(acc[ii][1] + s1*inv + bias[tj+1], 0.f),
                          fmaxf(acc[ii][2] + s2*inv + bias[tj+2], 0.f),
                          fmaxf(acc[ii][3] + s3*inv + bias[tj+3], 0.f) };
        size_t base = (size_t)row*BK;
        #pragma unroll
        for (int jj = 0; jj < 4; jj++) {
            float v = vals[jj];
            __nv_bfloat16 hi = __float2bfloat16(v);
            __nv_bfloat16 lo = __float2bfloat16(v - __bfloat162float(hi));
            g_mb[base + tj + jj]        = hi;
            g_mb[base + 64 + tj + jj]   = lo;
            g_mb[base + 128 + tj + jj]  = hi;
        }
    }
}

__global__ void k_gru()
{
    int i = blockIdx.x*blockDim.x + threadIdx.x;
    int n = i >> 6, j = i & 63;
    const float* gi = g_gi + n*192;
    const float* gh = g_gh + n*192;
    float r  = sigf(gi[j]      + gh[j]);
    float z  = sigf(gi[64+j]   + gh[64+j]);
    float nn = tanhf(gi[128+j] + r*gh[128+j]);
    float h  = g_out[i];
    float hn = (1.f - z)*nn + z*h;
    g_out[i] = hn;
    __nv_bfloat16 hi = __float2bfloat16(hn);
    __nv_bfloat16 lo = __float2bfloat16(hn - __bfloat162float(hi));
    size_t base = (size_t)n*BK;
    g_outb[base + j]       = hi;
    g_outb[base + 64 + j]  = lo;
    g_outb[base + 128 + j] = hi;
}

// Set2Set (6 steps) + memory LSTM; one block per graph
__global__ void __launch_bounds__(256)
k_s2s(const float* __restrict__ s2s_bih, const float* __restrict__ s2s_bhh,
      const float* __restrict__ mem_bih, const float* __restrict__ mem_bhh,
      float* __restrict__ d_out, int out_size)
{
    __shared__ float so[64*65];
    __shared__ float sq[128];
    __shared__ float shs[64], scs[64], sg[256], se[64];
    __shared__ float sred[2];
    int g = blockIdx.x, tid = threadIdx.x;
    for (int l = tid; l < 64*64; l += 256) {
        int n = l >> 6, c = l & 63;
        so[n*65+c] = g_out[(g*64+n)*64 + c];
    }
    if (tid < 128) sq[tid] = 0.f;
    if (tid < 64) { shs[tid] = 0.f; scs[tid] = 0.f; }
    __syncthreads();
    for (int step = 0; step < 6; step++) {
        float acc = s2s_bih[tid] + s2s_bhh[tid];
        #pragma unroll 4
        for (int k = 0; k < 128; k++) acc += sq[k]*g_s2s_wih_t[k*256+tid];
        #pragma unroll 4
        for (int k = 0; k < 64;  k++) acc += shs[k]*g_s2s_whh_t[k*256+tid];
        sg[tid] = acc;
        __syncthreads();
        if (tid < 64) {
            float iv = sg[tid], fv = sg[64+tid], gv = sg[128+tid], ov = sg[192+tid];
            float c = sigf(fv)*scs[tid] + sigf(iv)*tanhf(gv);
            scs[tid] = c;
            shs[tid] = sigf(ov)*tanhf(c);
        }
        __syncthreads();
        if (tid < 64) {
            float a = 0.f;
            #pragma unroll 8
            for (int k = 0; k < 64; k++) a += so[tid*65+k]*shs[k];
            se[tid] = a;
        }
        __syncthreads();
        if (tid < 32) {
            float m1 = fmaxf(se[tid], se[tid+32]);
            #pragma unroll
            for (int off = 16; off; off >>= 1) m1 = fmaxf(m1, __shfl_xor_sync(0xffffffffu, m1, off));
            if (tid == 0) sred[0] = m1;
        }
        __syncthreads();
        if (tid < 64) se[tid] = expf(se[tid] - sred[0]);
        __syncthreads();
        if (tid < 32) {
            float s1 = se[tid] + se[tid+32];
            #pragma unroll
            for (int off = 16; off; off >>= 1) s1 += __shfl_xor_sync(0xffffffffu, s1, off);
            if (tid == 0) sred[1] = s1;
        }
        __syncthreads();
        if (tid < 64) {
            float inv = 1.f/sred[1];
            float racc = 0.f;
            #pragma unroll 8
            for (int n = 0; n < 64; n++) racc += se[n]*so[n*65+tid];
            sq[64+tid] = racc*inv;
            sq[tid] = shs[tid];
        }
        __syncthreads();
    }
    float acc = mem_bih[tid] + mem_bhh[tid];
    #pragma unroll 4
    for (int k = 0; k < 128; k++) acc += sq[k]*g_mem_wih_t[k*256+tid];
    sg[tid] = acc;
    __syncthreads();
    if (tid < 64) {
        float iv = sg[tid], gv = sg[128+tid], ov = sg[192+tid];
        float cx = sigf(iv)*tanhf(gv);
        float hx = sigf(ov)*tanhf(cx);
        g_hx[g*64+tid] = hx;
        if (out_size >= NT*6 + 2*NG*D) {
            d_out[NT*6 + g*64 + tid]        = hx;
            d_out[NT*6 + NG*D + g*64 + tid] = cx;
        }
    }
}

// head
__global__ void __launch_bounds__(64)
k_final(const int* __restrict__ nonring, const int* __restrict__ nrbidx,
        const float* __restrict__ lin1_b, const float* __restrict__ lin2_w,
        const float* __restrict__ lin2_b, float* __restrict__ d_out)
{
    __shared__ float sf[320];
    __shared__ float so1[64];
    int r = blockIdx.x, tid = threadIdx.x;
    int ch = r / 48;
    int t  = (r % 48) * 64 + tid;
    sf[tid*5 + 0] = g_hx[nrbidx[t]*64 + ch];
    #pragma unroll
    for (int s = 1; s < 5; s++) {
        int node = nonring[(s-1)*NT + t];
        sf[tid*5 + s] = g_out[node*64 + ch];
    }
    __syncthreads();
    float acc = lin1_b[tid];
    #pragma unroll 8
    for (int q = 0; q < 320; q++) acc += sf[q]*g_lin1_t[q*64+tid];
    so1[tid] = fmaxf(acc, 0.f);
    __syncthreads();
    if (tid < 6) {
        float a2 = lin2_b[tid];
        #pragma unroll 8
        for (int k = 0; k < 64; k++) a2 += so1[k]*lin2_w[tid*64+k];
        d_out[r*6 + tid] = a2;
    }
}

extern "C" void kernel_launch(void* const* d_in, const int* in_sizes, int n_in,
                              void* d_out, int out_size)
{
    const float* x        = (const float*)d_in[0];
    const float* ea       = (const float*)d_in[1];
    const int*   eidx     = (const int*)  d_in[2];
    const int*   nonring  = (const int*)  d_in[4];
    const int*   nrbidx   = (const int*)  d_in[5];
    int base = (n_in >= 32) ? 8 : 6;
    const float* lin0_w  = (const float*)d_in[base+0];
    const float* lin0_b  = (const float*)d_in[base+1];
    const float* e1_w    = (const float*)d_in[base+2];
    const float* e1_b    = (const float*)d_in[base+3];
    const float* e2_w    = (const float*)d_in[base+4];
    const float* e2_b    = (const float*)d_in[base+5];
    const float* root_w  = (const float*)d_in[base+6];
    const float* conv_b  = (const float*)d_in[base+7];
    const float* gru_wih = (const float*)d_in[base+8];
    const float* gru_whh = (const float*)d_in[base+9];
    const float* gru_bih = (const float*)d_in[base+10];
    const float* gru_bhh = (const float*)d_in[base+11];
    const float* s2s_wih = (const float*)d_in[base+12];
    const float* s2s_whh = (const float*)d_in[base+13];
    const float* s2s_bih = (const float*)d_in[base+14];
    const float* s2s_bhh = (const float*)d_in[base+15];
    const float* mem_wih = (const float*)d_in[base+16];
    const float* mem_bih = (const float*)d_in[base+18];
    const float* mem_bhh = (const float*)d_in[base+19];
    const float* lin1_w  = (const float*)d_in[base+20];
    const float* lin1_b  = (const float*)d_in[base+21];
    const float* lin2_w  = (const float*)d_in[base+22];
    const float* lin2_b  = (const float*)d_in[base+23];
    float* out = (float*)d_out;

    const int* src = eidx;
    const int* dst = eidx + N_EDGES;

    const int BUILD_SMEM = 256 * ROWB;       // 102400 bytes
    const int GIH_SMEM   = 192 * ROWB;       // 76800 bytes
    static int init_done = 0;
    static cudaStream_t sB;
    static cudaEvent_t evA, evJ, evG;
    if (!init_done) {
        cudaFuncSetAttribute(k_build_ew, cudaFuncAttributeMaxDynamicSharedMemorySize, BUILD_SMEM);
        cudaFuncSetAttribute(k_gih_h,    cudaFuncAttributeMaxDynamicSharedMemorySize, GIH_SMEM);
        cudaStreamCreateWithFlags(&sB, cudaStreamNonBlocking);
        cudaEventCreateWithFlags(&evA, cudaEventDisableTiming);
        cudaEventCreateWithFlags(&evJ, cudaEventDisableTiming);
        cudaEventCreateWithFlags(&evG, cudaEventDisableTiming);
        init_done = 1;
    }

    k_prep_all<<<(N_EDGES*D)/256, 256>>>(gru_wih, gru_whh, s2s_wih, s2s_whh, mem_wih,
                                         lin1_w, e2_w, x, lin0_w, lin0_b, ea, e1_w, e1_b);
    cudaEventRecord(evA, 0);
    cudaStreamWaitEvent(sB, evA, 0);
    // CSR chain + first gh on side stream, overlapping the big build
    k_count<<<N_EDGES/256, 256, 0, sB>>>(dst);
    k_scan<<<1, 1024, 0, sB>>>();
    k_fill<<<N_EDGES/256, 256, 0, sB>>>(dst);
    k_gih_h<<<dim3(N_NODES/128, 3), 128, GIH_SMEM, sB>>>(gru_bih, gru_bhh, 1);  // gh(0)
    cudaEventRecord(evJ, sB);
    k_build_ew<<<dim3(N_EDGES/128, 4096/128), 128, BUILD_SMEM>>>(e2_b);         // stream 0

    for (int it = 0; it < 6; it++) {
        k_msg_w<<<N_EDGES/8, 256>>>(src);
        cudaStreamWaitEvent(0, evJ, 0);     // gh(it) [+ CSR fill at it=0] complete
        k_gemm1<<<N_NODES/64, 256>>>(root_w, conv_b);
        k_gih_h<<<dim3(N_NODES/128, 3), 128, GIH_SMEM>>>(gru_bih, gru_bhh, 0);  // gi(it)
        k_gru<<<(N_NODES*D)/256, 256>>>();
        if (it < 5) {
            cudaEventRecord(evG, 0);
            cudaStreamWaitEvent(sB, evG, 0);
            k_gih_h<<<dim3(N_NODES/128, 3), 128, GIH_SMEM, sB>>>(gru_bih, gru_bhh, 1);  // gh(it+1)
            cudaEventRecord(evJ, sB);
        }
    }

    k_s2s<<<NG, 256>>>(s2s_bih, s2s_bhh, mem_bih, mem_bhh, out, out_size);
    k_final<<<NT, 64>>>(nonring, nrbidx, lin1_b, lin2_w, lin2_b, out);
}